// round 15
// baseline (speedup 1.0000x reference)
#include <cuda_runtime.h>
#include <cuda_bf16.h>

#define BATCH 2
#define NSEQ  2048
#define DIMM  1024
#define NH    8
#define DH    64
#define NE    8
#define TTOK  (BATCH*NSEQ)     /* 4096 */
#define BH    (BATCH*NH)       /* 16 */
#define GCOLS (NH*NE)          /* 64 */

typedef unsigned long long ull;

// ---------------- warp-MMA helpers ----------------
__device__ __forceinline__ unsigned smem_u32(const void* p) {
    unsigned a;
    asm("{ .reg .u64 t; cvta.to.shared.u64 t, %1; cvt.u32.u64 %0, t; }" : "=r"(a) : "l"(p));
    return a;
}
__device__ __forceinline__ void ldsm_x4(unsigned& r0, unsigned& r1, unsigned& r2, unsigned& r3,
                                        unsigned addr) {
    asm volatile("ldmatrix.sync.aligned.m8n8.x4.shared.b16 {%0,%1,%2,%3}, [%4];"
                 : "=r"(r0), "=r"(r1), "=r"(r2), "=r"(r3) : "r"(addr));
}
__device__ __forceinline__ void ldsm_x2t(unsigned& r0, unsigned& r1, unsigned addr) {
    asm volatile("ldmatrix.sync.aligned.m8n8.x2.trans.shared.b16 {%0,%1}, [%2];"
                 : "=r"(r0), "=r"(r1) : "r"(addr));
}
__device__ __forceinline__ void mma_bf16(float* c,
                                         unsigned a0, unsigned a1, unsigned a2, unsigned a3,
                                         unsigned b0, unsigned b1) {
    asm volatile("mma.sync.aligned.m16n8k16.row.col.f32.bf16.bf16.f32 "
                 "{%0,%1,%2,%3}, {%4,%5,%6,%7}, {%8,%9}, {%0,%1,%2,%3};"
                 : "+f"(c[0]), "+f"(c[1]), "+f"(c[2]), "+f"(c[3])
                 : "r"(a0), "r"(a1), "r"(a2), "r"(a3), "r"(b0), "r"(b1));
}
// split two fp32 into hi/lo bf16x2
__device__ __forceinline__ void split2(float a, float b,
                                       __nv_bfloat162& h2, __nv_bfloat162& l2) {
    __nv_bfloat16 ha = __float2bfloat16_rn(a);
    __nv_bfloat16 hb = __float2bfloat16_rn(b);
    h2 = __halves2bfloat162(ha, hb);
    l2 = __floats2bfloat162_rn(a - __bfloat162float(ha), b - __bfloat162float(hb));
}

// ---------------- scratch ----------------
static __device__ float g_gpart[8][TTOK*GCOLS];
static __device__ float g_gate[BH*NSEQ];
static __device__ int   g_cnt[NH*NE];
static __device__ int   g_list[NH*NE*TTOK];
static __device__ float g_outh[(size_t)BH*NSEQ*DIMM];
// pre-split bf16 hi/lo
static __device__ __nv_bfloat16 g_xh[TTOK*DIMM],  g_xl[TTOK*DIMM];
static __device__ __nv_bfloat16 g_wqh[1024*512],  g_wql[1024*512];
static __device__ __nv_bfloat16 g_wkh[1024*512],  g_wkl[1024*512];
static __device__ __nv_bfloat16 g_veh[64*DIMM*DH], g_vel[64*DIMM*DH];
static __device__ __nv_bfloat16 g_oeh[64*DH*DIMM], g_oel[64*DH*DIMM];
static __device__ __nv_bfloat16 g_qh[BH*NSEQ*DH], g_ql[BH*NSEQ*DH];
static __device__ __nv_bfloat16 g_kh[BH*NSEQ*DH], g_kl[BH*NSEQ*DH];
static __device__ __nv_bfloat16 g_valsh[BH*NSEQ*DH], g_valsl[BH*NSEQ*DH];
static __device__ __nv_bfloat16 g_attnh[BH*NSEQ*DH], g_attnl[BH*NSEQ*DH];

__global__ void init_kernel() {
    int i = threadIdx.x;
    if (i < NH*NE) g_cnt[i] = 0;
}

// ---------------- elementwise fp32 -> bf16 hi/lo split ----------------
__global__ void split_kernel(const float* __restrict__ src,
                             __nv_bfloat16* __restrict__ hi,
                             __nv_bfloat16* __restrict__ lo, int npairs) {
    int i = blockIdx.x * blockDim.x + threadIdx.x;
    if (i >= npairs) return;
    float2 v = ((const float2*)src)[i];
    __nv_bfloat162 h2, l2;
    split2(v.x, v.y, h2, l2);
    ((__nv_bfloat162*)hi)[i] = h2;
    ((__nv_bfloat162*)lo)[i] = l2;
}

// ---------------- smem layout for GEMM-MMA kernels (bytes) ----------------
#define LDA   72
#define SM_TS   0
#define SM_GTS  512
#define SM_AHI  1024
#define SM_ALO  (SM_AHI + 128*LDA*2)
#define SM_BHI  (SM_ALO + 128*LDA*2)
#define SM_BLO  (SM_BHI + 64*LDA*2)
#define TENS_SMEM (SM_BLO + 64*LDA*2)   /* 56320 */

// warp compute over one 64-K chunk: 4 ksteps x (2m x 4n) x 3 split terms
__device__ __forceinline__ void mma_chunk(float c[2][4][4], unsigned sb,
                                          int wm, int wn, int lane) {
#pragma unroll
    for (int ks = 0; ks < 4; ks++) {
        int k0 = ks * 16;
        unsigned ah[2][4], al[2][4], bh[4][2], bl[4][2];
#pragma unroll
        for (int mt = 0; mt < 2; mt++) {
            int row = wm*32 + mt*16 + (lane & 15);
            unsigned off = (unsigned)(row*LDA + k0 + (lane >> 4)*8) * 2;
            ldsm_x4(ah[mt][0], ah[mt][1], ah[mt][2], ah[mt][3], sb + SM_AHI + off);
            ldsm_x4(al[mt][0], al[mt][1], al[mt][2], al[mt][3], sb + SM_ALO + off);
        }
#pragma unroll
        for (int nt = 0; nt < 4; nt++) {
            int n0 = wn*32 + nt*8;
            unsigned off = (unsigned)((k0 + (lane & 15))*LDA + n0) * 2;
            ldsm_x2t(bh[nt][0], bh[nt][1], sb + SM_BHI + off);
            ldsm_x2t(bl[nt][0], bl[nt][1], sb + SM_BLO + off);
        }
#pragma unroll
        for (int mt = 0; mt < 2; mt++)
#pragma unroll
            for (int nt = 0; nt < 4; nt++) {
                mma_bf16(c[mt][nt], ah[mt][0], ah[mt][1], ah[mt][2], ah[mt][3],
                         bh[nt][0], bh[nt][1]);
                mma_bf16(c[mt][nt], ah[mt][0], ah[mt][1], ah[mt][2], ah[mt][3],
                         bl[nt][0], bl[nt][1]);
                mma_bf16(c[mt][nt], al[mt][0], al[mt][1], al[mt][2], al[mt][3],
                         bh[nt][0], bh[nt][1]);
            }
    }
}

// ---------------- kernel 1: proj Q/K via warp MMA (pre-split operands) ----------------
__global__ void __launch_bounds__(256, 2)
projt_kernel() {
    extern __shared__ __align__(128) char smem[];
    unsigned sb = smem_u32(smem);
    int tid = threadIdx.x, wid = tid >> 5, lane = tid & 31;
    int bm = blockIdx.x, bn = blockIdx.y;
    int wm = wid & 3, wn = wid >> 2;
    const __nv_bfloat16* Wh = (bn < 8) ? g_wqh : g_wkh;
    const __nv_bfloat16* Wl = (bn < 8) ? g_wql : g_wkl;
    int colbase = (bn & 7) * 64;

    float c[2][4][4] = {};
    for (int ch = 0; ch < 16; ch++) {
        if (ch) __syncthreads();
#pragma unroll
        for (int r = 0; r < 4; r++) {
            int task = tid + 256*r;
            int row = task >> 3, kg = task & 7;
            size_t off = (size_t)(bm*128 + row)*DIMM + ch*64 + kg*8;
            unsigned so = (unsigned)(row*LDA + kg*8)*2;
            *(uint4*)(smem + SM_AHI + so) = *(const uint4*)&g_xh[off];
            *(uint4*)(smem + SM_ALO + so) = *(const uint4*)&g_xl[off];
        }
#pragma unroll
        for (int r = 0; r < 2; r++) {
            int task = tid + 256*r;
            int krow = task >> 3, ng = task & 7;
            size_t off = (size_t)(ch*64 + krow)*512 + colbase + ng*8;
            unsigned so = (unsigned)(krow*LDA + ng*8)*2;
            *(uint4*)(smem + SM_BHI + so) = *(const uint4*)&Wh[off];
            *(uint4*)(smem + SM_BLO + so) = *(const uint4*)&Wl[off];
        }
        __syncthreads();
        mma_chunk(c, sb, wm, wn, lane);
    }
    const float S = 0.125f;
#pragma unroll
    for (int mt = 0; mt < 2; mt++)
#pragma unroll
        for (int nt = 0; nt < 4; nt++) {
            int r0 = bm*128 + wm*32 + mt*16 + (lane >> 2);
            int col = bn*64 + wn*32 + nt*8 + (lane & 3)*2;
            int b0_ = r0 >> 11, n0_ = r0 & 2047;
            int b1_ = (r0+8) >> 11, n1_ = (r0+8) & 2047;
            __nv_bfloat162 h2, l2;
            if (col < 512) {
                size_t i0 = ((size_t)(b0_*NH + (col >> 6))*NSEQ + n0_)*DH + (col & 63);
                size_t i1 = ((size_t)(b1_*NH + (col >> 6))*NSEQ + n1_)*DH + (col & 63);
                split2(c[mt][nt][0]*S, c[mt][nt][1]*S, h2, l2);
                *(__nv_bfloat162*)&g_qh[i0] = h2; *(__nv_bfloat162*)&g_ql[i0] = l2;
                split2(c[mt][nt][2]*S, c[mt][nt][3]*S, h2, l2);
                *(__nv_bfloat162*)&g_qh[i1] = h2; *(__nv_bfloat162*)&g_ql[i1] = l2;
            } else {
                int c2 = col - 512;
                size_t i0 = ((size_t)(b0_*NH + (c2 >> 6))*NSEQ + n0_)*DH + (c2 & 63);
                size_t i1 = ((size_t)(b1_*NH + (c2 >> 6))*NSEQ + n1_)*DH + (c2 & 63);
                split2(c[mt][nt][0], c[mt][nt][1], h2, l2);
                *(__nv_bfloat162*)&g_kh[i0] = h2; *(__nv_bfloat162*)&g_kl[i0] = l2;
                split2(c[mt][nt][2], c[mt][nt][3], h2, l2);
                *(__nv_bfloat162*)&g_kh[i1] = h2; *(__nv_bfloat162*)&g_kl[i1] = l2;
            }
        }
}

// ---------------- kernel 2: fp32 gate logits (split-K, exact routing) ----------------
__global__ void glogit_kernel(const float* __restrict__ x, const float* __restrict__ wg) {
    __shared__ float As[16][132];
    __shared__ float Bs[16][68];
    int tid = threadIdx.x;
    int bm = blockIdx.x, kz = blockIdx.y;
    int ty = tid >> 4, tx = tid & 15;
    float acc[8][4] = {};
    for (int kc = 0; kc < 8; kc++) {
#pragma unroll
        for (int r = 0; r < 8; r++) {
            int idx = tid + 256*r;
            int tok = idx >> 4, k = idx & 15;
            As[k][tok] = x[(size_t)(bm*128 + tok)*DIMM + kz*128 + kc*16 + k];
        }
#pragma unroll
        for (int r = 0; r < 4; r++) {
            int idx = tid + 256*r;
            int k = idx >> 6, c2 = idx & 63;
            Bs[k][c2] = wg[(size_t)(kz*128 + kc*16 + k)*GCOLS + c2];
        }
        __syncthreads();
#pragma unroll
        for (int k = 0; k < 16; k++) {
            float a_[8], b_[4];
#pragma unroll
            for (int i = 0; i < 8; i++) a_[i] = As[k][ty*8 + i];
#pragma unroll
            for (int j = 0; j < 4; j++) b_[j] = Bs[k][tx*4 + j];
#pragma unroll
            for (int i = 0; i < 8; i++)
#pragma unroll
                for (int j = 0; j < 4; j++)
                    acc[i][j] += a_[i] * b_[j];
        }
        __syncthreads();
    }
#pragma unroll
    for (int i = 0; i < 8; i++)
#pragma unroll
        for (int j = 0; j < 4; j++)
            g_gpart[kz][(size_t)(bm*128 + ty*8 + i)*GCOLS + tx*4 + j] = acc[i][j];
}

// ---------------- kernel 3: gate sigmoid + argmax + bucket append ----------------
__global__ void gate_kernel() {
    int id = blockIdx.x * blockDim.x + threadIdx.x;
    if (id >= TTOK*NH) return;
    int t = id / NH, h = id % NH;
    float lg[NE] = {};
#pragma unroll
    for (int kz = 0; kz < 8; kz++) {
        const float* gp = &g_gpart[kz][(size_t)t*GCOLS + h*NE];
        float4 a = *(const float4*)gp, b = *(const float4*)(gp + 4);
        lg[0]+=a.x; lg[1]+=a.y; lg[2]+=a.z; lg[3]+=a.w;
        lg[4]+=b.x; lg[5]+=b.y; lg[6]+=b.z; lg[7]+=b.w;
    }
    float best = lg[0]; int be = 0;
#pragma unroll
    for (int e = 1; e < NE; e++) { if (lg[e] > best) { best = lg[e]; be = e; } }
    float gate = 1.f / (1.f + __expf(-best));
    int b_ = t >> 11, n = t & 2047;
    g_gate[(size_t)(b_*NH + h)*NSEQ + n] = gate;
    int pos = atomicAdd(&g_cnt[h*NE + be], 1);
    g_list[(size_t)(h*NE + be)*TTOK + pos] = t;
}

// ---------------- kernel 4: value-expert GEMM (gate applied at epilogue) ----------------
__global__ void __launch_bounds__(256, 2)
valt_kernel() {
    extern __shared__ __align__(128) char smem[];
    int he = blockIdx.x; int h = he >> 3, e = he & 7;
    int cnt = g_cnt[he];
    int start = blockIdx.y * 128;
    if (start >= cnt) return;
    unsigned sb = smem_u32(smem);
    int tid = threadIdx.x, wid = tid >> 5, lane = tid & 31;
    int wm = wid & 3, wn = wid >> 2;
    int* ts = (int*)(smem + SM_TS);
    float* gts = (float*)(smem + SM_GTS);
    if (tid < 128) {
        int t = (start + tid < cnt) ? g_list[(size_t)he*TTOK + start + tid] : -1;
        ts[tid] = t;
        gts[tid] = (t >= 0) ? g_gate[(size_t)((t>>11)*NH + h)*NSEQ + (t & 2047)] : 0.f;
    }
    __syncthreads();
    const __nv_bfloat16* Bh = g_veh + (size_t)(e*NH + h)*DIMM*DH;
    const __nv_bfloat16* Bl = g_vel + (size_t)(e*NH + h)*DIMM*DH;

    float c[2][4][4] = {};
    for (int ch = 0; ch < 16; ch++) {
        if (ch) __syncthreads();
#pragma unroll
        for (int r = 0; r < 4; r++) {
            int task = tid + 256*r;
            int row = task >> 3, kg = task & 7;
            int t = ts[row];
            unsigned so = (unsigned)(row*LDA + kg*8)*2;
            if (t >= 0) {
                size_t off = (size_t)t*DIMM + ch*64 + kg*8;
                *(uint4*)(smem + SM_AHI + so) = *(const uint4*)&g_xh[off];
                *(uint4*)(smem + SM_ALO + so) = *(const uint4*)&g_xl[off];
            } else {
                uint4 z = make_uint4(0,0,0,0);
                *(uint4*)(smem + SM_AHI + so) = z;
                *(uint4*)(smem + SM_ALO + so) = z;
            }
        }
#pragma unroll
        for (int r = 0; r < 2; r++) {
            int task = tid + 256*r;
            int krow = task >> 3, ng = task & 7;
            size_t off = (size_t)(ch*64 + krow)*DH + ng*8;
            unsigned so = (unsigned)(krow*LDA + ng*8)*2;
            *(uint4*)(smem + SM_BHI + so) = *(const uint4*)&Bh[off];
            *(uint4*)(smem + SM_BLO + so) = *(const uint4*)&Bl[off];
        }
        __syncthreads();
        mma_chunk(c, sb, wm, wn, lane);
    }
#pragma unroll
    for (int mt = 0; mt < 2; mt++)
#pragma unroll
        for (int nt = 0; nt < 4; nt++) {
            int col = wn*32 + nt*8 + (lane & 3)*2;
            int r0 = wm*32 + mt*16 + (lane >> 2);
            int t0 = ts[r0], t1 = ts[r0 + 8];
            __nv_bfloat162 h2, l2;
            if (t0 >= 0) {
                float g = gts[r0];
                size_t base = (((size_t)(t0>>11)*NH + h)*NSEQ + (t0 & 2047))*DH + col;
                split2(c[mt][nt][0]*g, c[mt][nt][1]*g, h2, l2);
                *(__nv_bfloat162*)&g_valsh[base] = h2;
                *(__nv_bfloat162*)&g_valsl[base] = l2;
            }
            if (t1 >= 0) {
                float g = gts[r0 + 8];
                size_t base = (((size_t)(t1>>11)*NH + h)*NSEQ + (t1 & 2047))*DH + col;
                split2(c[mt][nt][2]*g, c[mt][nt][3]*g, h2, l2);
                *(__nv_bfloat162*)&g_valsh[base] = h2;
                *(__nv_bfloat162*)&g_valsl[base] = l2;
            }
        }
}

// ---------------- kernel 5: causal flash attention (pre-split staging) ----------------
#define LDQT 136
#define LDP  72
#define LDPS 68
#define AT_QTH 0
#define AT_QTL (AT_QTH + 64*LDQT*2)
#define AT_KH  (AT_QTL + 64*LDQT*2)
#define AT_KL  (AT_KH + 64*LDP*2)
#define AT_VH  (AT_KL + 64*LDP*2)
#define AT_VL  (AT_VH + 64*LDP*2)
#define AT_PH  (AT_VL + 64*LDP*2)
#define AT_PL  (AT_PH + 128*LDP*2)
#define AT_PS  (AT_PL + 128*LDP*2)
#define AT_M   (AT_PS + 128*LDPS*4)
#define AT_L   (AT_M + 512)
#define AT_F   (AT_L + 512)
#define ATTN2_SMEM (AT_F + 512)          /* 144896 */

__global__ void __launch_bounds__(256, 1)
attn_kernel() {
    extern __shared__ __align__(128) char smem[];
    unsigned sb = smem_u32(smem);
    float* Ps  = (float*)(smem + AT_PS);
    float* m_s = (float*)(smem + AT_M);
    float* l_s = (float*)(smem + AT_L);
    float* f_s = (float*)(smem + AT_F);
    int bh = blockIdx.x;
    int qt = (int)(gridDim.y - 1) - (int)blockIdx.y;
    int qbase = qt * 128;
    int tid = threadIdx.x, wid = tid >> 5, lane = tid & 31;
    int wm = wid & 3, wn = wid >> 2;
    int wmS = wid & 1, wnS = wid >> 1;

    // stage Q^T (already scaled & split at projt): transposed bf16 scatter
#pragma unroll
    for (int r = 0; r < 4; r++) {
        int task = tid + 256*r;
        int row = task >> 3, d0 = (task & 7)*8;
        size_t off = ((size_t)bh*NSEQ + qbase + row)*DH + d0;
        uint4 hv = *(const uint4*)&g_qh[off];
        uint4 lv = *(const uint4*)&g_ql[off];
        const __nv_bfloat162* hp = (const __nv_bfloat162*)&hv;
        const __nv_bfloat162* lp = (const __nv_bfloat162*)&lv;
#pragma unroll
        for (int i = 0; i < 4; i++) {
            *(__nv_bfloat16*)(smem + AT_QTH + ((size_t)(d0+2*i)*LDQT + row)*2)   = __low2bfloat16(hp[i]);
            *(__nv_bfloat16*)(smem + AT_QTH + ((size_t)(d0+2*i+1)*LDQT + row)*2) = __high2bfloat16(hp[i]);
            *(__nv_bfloat16*)(smem + AT_QTL + ((size_t)(d0+2*i)*LDQT + row)*2)   = __low2bfloat16(lp[i]);
            *(__nv_bfloat16*)(smem + AT_QTL + ((size_t)(d0+2*i+1)*LDQT + row)*2) = __high2bfloat16(lp[i]);
        }
    }
    if (tid < 128) { m_s[tid] = -1e30f; l_s[tid] = 0.f; }

    float o[2][4][4] = {};
    int ntiles = qt*2 + 2;
    for (int jt = 0; jt < ntiles; jt++) {
        __syncthreads();
#pragma unroll
        for (int r = 0; r < 2; r++) {
            int task = tid + 256*r;
            int j = task >> 3, d0 = (task & 7)*8;
            size_t off = ((size_t)bh*NSEQ + jt*64 + j)*DH + d0;
            unsigned so = (unsigned)(j*LDP + d0)*2;
            *(uint4*)(smem + AT_KH + so) = *(const uint4*)&g_kh[off];
            *(uint4*)(smem + AT_KL + so) = *(const uint4*)&g_kl[off];
            *(uint4*)(smem + AT_VH + so) = *(const uint4*)&g_valsh[off];
            *(uint4*)(smem + AT_VL + so) = *(const uint4*)&g_valsl[off];
        }
        __syncthreads();
        // S^T mma: A=K [kv][d], B=Q^T [d][q]
        float s[2][4][4] = {};
#pragma unroll
        for (int ks = 0; ks < 4; ks++) {
            int k0 = ks * 16;
            unsigned ah[2][4], al[2][4], bh2[4][2], bl2[4][2];
#pragma unroll
            for (int mt = 0; mt < 2; mt++) {
                int row = wmS*32 + mt*16 + (lane & 15);
                unsigned off = (unsigned)(row*LDP + k0 + (lane >> 4)*8) * 2;
                ldsm_x4(ah[mt][0], ah[mt][1], ah[mt][2], ah[mt][3], sb + AT_KH + off);
                ldsm_x4(al[mt][0], al[mt][1], al[mt][2], al[mt][3], sb + AT_KL + off);
            }
#pragma unroll
            for (int nt = 0; nt < 4; nt++) {
                int n0 = wnS*32 + nt*8;
                unsigned off = (unsigned)((k0 + (lane & 15))*LDQT + n0) * 2;
                ldsm_x2t(bh2[nt][0], bh2[nt][1], sb + AT_QTH + off);
                ldsm_x2t(bl2[nt][0], bl2[nt][1], sb + AT_QTL + off);
            }
#pragma unroll
            for (int mt = 0; mt < 2; mt++)
#pragma unroll
                for (int nt = 0; nt < 4; nt++) {
                    mma_bf16(s[mt][nt], ah[mt][0], ah[mt][1], ah[mt][2], ah[mt][3],
                             bh2[nt][0], bh2[nt][1]);
                    mma_bf16(s[mt][nt], ah[mt][0], ah[mt][1], ah[mt][2], ah[mt][3],
                             bl2[nt][0], bl2[nt][1]);
                    mma_bf16(s[mt][nt], al[mt][0], al[mt][1], al[mt][2], al[mt][3],
                             bh2[nt][0], bh2[nt][1]);
                }
        }
        bool diag = (jt*64 + 63 > qbase);
#pragma unroll
        for (int mt = 0; mt < 2; mt++)
#pragma unroll
            for (int nt = 0; nt < 4; nt++) {
                int kvr = wmS*32 + mt*16 + (lane >> 2);
                int q0  = wnS*32 + nt*8 + (lane & 3)*2;
                if (diag) {
                    int kg = jt*64 + kvr, qg = qbase + q0;
                    if (kg > qg)       s[mt][nt][0] = -1e30f;
                    if (kg > qg+1)     s[mt][nt][1] = -1e30f;
                    if (kg+8 > qg)     s[mt][nt][2] = -1e30f;
                    if (kg+8 > qg+1)   s[mt][nt][3] = -1e30f;
                }
                Ps[q0*LDPS + kvr]       = s[mt][nt][0];
                Ps[(q0+1)*LDPS + kvr]   = s[mt][nt][1];
                Ps[q0*LDPS + kvr+8]     = s[mt][nt][2];
                Ps[(q0+1)*LDPS + kvr+8] = s[mt][nt][3];
            }
        __syncthreads();
        // online softmax (2 thr/row) + emit P split bf16
        {
            int row = tid >> 1, half = tid & 1;
            float* P = &Ps[row*LDPS + half*32];
            float mx = m_s[row];
#pragma unroll 8
            for (int j2 = 0; j2 < 32; j2++) mx = fmaxf(mx, P[j2]);
            mx = fmaxf(mx, __shfl_xor_sync(0xffffffffu, mx, 1));
            float sum = 0.f;
            __nv_bfloat162* PH2 = (__nv_bfloat162*)(smem + AT_PH + (size_t)(row*LDP + half*32)*2);
            __nv_bfloat162* PL2 = (__nv_bfloat162*)(smem + AT_PL + (size_t)(row*LDP + half*32)*2);
#pragma unroll 4
            for (int j2 = 0; j2 < 32; j2 += 2) {
                float p0 = __expf(P[j2] - mx);
                float p1 = __expf(P[j2+1] - mx);
                sum += p0 + p1;
                __nv_bfloat162 h2, l2;
                split2(p0, p1, h2, l2);
                PH2[j2 >> 1] = h2;
                PL2[j2 >> 1] = l2;
            }
            sum += __shfl_xor_sync(0xffffffffu, sum, 1);
            if (half == 0) {
                float mo = m_s[row];
                float f = __expf(mo - mx);
                m_s[row] = mx;
                l_s[row] = l_s[row]*f + sum;
                f_s[row] = f;
            }
        }
        __syncthreads();
#pragma unroll
        for (int mt = 0; mt < 2; mt++) {
            int r0 = wm*32 + mt*16 + (lane >> 2);
            float f0 = f_s[r0], f1 = f_s[r0 + 8];
#pragma unroll
            for (int nt = 0; nt < 4; nt++) {
                o[mt][nt][0] *= f0; o[mt][nt][1] *= f0;
                o[mt][nt][2] *= f1; o[mt][nt][3] *= f1;
            }
        }
#pragma unroll
        for (int ks = 0; ks < 4; ks++) {
            int k0 = ks * 16;
            unsigned ah[2][4], al[2][4], bh2[4][2], bl2[4][2];
#pragma unroll
            for (int mt = 0; mt < 2; mt++) {
                int row = wm*32 + mt*16 + (lane & 15);
                unsigned off = (unsigned)(row*LDP + k0 + (lane >> 4)*8) * 2;
                ldsm_x4(ah[mt][0], ah[mt][1], ah[mt][2], ah[mt][3], sb + AT_PH + off);
                ldsm_x4(al[mt][0], al[mt][1], al[mt][2], al[mt][3], sb + AT_PL + off);
            }
#pragma unroll
            for (int nt = 0; nt < 4; nt++) {
                int n0 = wn*32 + nt*8;
                unsigned off = (unsigned)((k0 + (lane & 15))*LDP + n0) * 2;
                ldsm_x2t(bh2[nt][0], bh2[nt][1], sb + AT_VH + off);
                ldsm_x2t(bl2[nt][0], bl2[nt][1], sb + AT_VL + off);
            }
#pragma unroll
            for (int mt = 0; mt < 2; mt++)
#pragma unroll
                for (int nt = 0; nt < 4; nt++) {
                    mma_bf16(o[mt][nt], ah[mt][0], ah[mt][1], ah[mt][2], ah[mt][3],
                             bh2[nt][0], bh2[nt][1]);
                    mma_bf16(o[mt][nt], ah[mt][0], ah[mt][1], ah[mt][2], ah[mt][3],
                             bl2[nt][0], bl2[nt][1]);
                    mma_bf16(o[mt][nt], al[mt][0], al[mt][1], al[mt][2], al[mt][3],
                             bh2[nt][0], bh2[nt][1]);
                }
        }
    }
    // epilogue: divide by l, split-write
#pragma unroll
    for (int mt = 0; mt < 2; mt++) {
        int r0 = wm*32 + mt*16 + (lane >> 2);
        float inv0 = 1.f / l_s[r0], inv1 = 1.f / l_s[r0 + 8];
#pragma unroll
        for (int nt = 0; nt < 4; nt++) {
            int col = wn*32 + nt*8 + (lane & 3)*2;
            size_t i0 = ((size_t)bh*NSEQ + qbase + r0)*DH + col;
            size_t i1 = ((size_t)bh*NSEQ + qbase + r0 + 8)*DH + col;
            __nv_bfloat162 h2, l2;
            split2(o[mt][nt][0]*inv0, o[mt][nt][1]*inv0, h2, l2);
            *(__nv_bfloat162*)&g_attnh[i0] = h2; *(__nv_bfloat162*)&g_attnl[i0] = l2;
            split2(o[mt][nt][2]*inv1, o[mt][nt][3]*inv1, h2, l2);
            *(__nv_bfloat162*)&g_attnh[i1] = h2; *(__nv_bfloat162*)&g_attnl[i1] = l2;
        }
    }
}

// ---------------- kernel 6: output-expert GEMM (gate at epilogue, 4 tiles/block) ----------------
__global__ void __launch_bounds__(256, 2)
outt_kernel() {
    extern __shared__ __align__(128) char smem[];
    int he = blockIdx.x; int h = he >> 3, e = he & 7;
    int cnt = g_cnt[he];
    int start = blockIdx.y * 128;
    if (start >= cnt) return;
    int ct0 = blockIdx.z * 4;
    unsigned sb = smem_u32(smem);
    int tid = threadIdx.x, wid = tid >> 5, lane = tid & 31;
    int wm = wid & 3, wn = wid >> 2;
    int* ts = (int*)(smem + SM_TS);
    float* gts = (float*)(smem + SM_GTS);
    if (tid < 128) {
        int t = (start + tid < cnt) ? g_list[(size_t)he*TTOK + start + tid] : -1;
        ts[tid] = t;
        gts[tid] = (t >= 0) ? g_gate[(size_t)((t>>11)*NH + h)*NSEQ + (t & 2047)] : 0.f;
    }
    __syncthreads();
    const __nv_bfloat16* Bh = g_oeh + (size_t)(e*NH + h)*DH*DIMM;
    const __nv_bfloat16* Bl = g_oel + (size_t)(e*NH + h)*DH*DIMM;

    // stage A once (attn rows, no gate)
#pragma unroll
    for (int r = 0; r < 4; r++) {
        int task = tid + 256*r;
        int row = task >> 3, kg = task & 7;
        int t = ts[row];
        unsigned so = (unsigned)(row*LDA + kg*8)*2;
        if (t >= 0) {
            size_t off = (((size_t)(t>>11)*NH + h)*NSEQ + (t & 2047))*DH + kg*8;
            *(uint4*)(smem + SM_AHI + so) = *(const uint4*)&g_attnh[off];
            *(uint4*)(smem + SM_ALO + so) = *(const uint4*)&g_attnl[off];
        } else {
            uint4 z = make_uint4(0,0,0,0);
            *(uint4*)(smem + SM_AHI + so) = z;
            *(uint4*)(smem + SM_ALO + so) = z;
        }
    }

    for (int i = 0; i < 4; i++) {
        int ct = ct0 + i;
        __syncthreads();
#pragma unroll
        for (int r = 0; r < 2; r++) {
            int task = tid + 256*r;
            int krow = task >> 3, ng = task & 7;
            size_t off = (size_t)krow*DIMM + ct*64 + ng*8;
            unsigned so = (unsigned)(krow*LDA + ng*8)*2;
            *(uint4*)(smem + SM_BHI + so) = *(const uint4*)&Bh[off];
            *(uint4*)(smem + SM_BLO + so) = *(const uint4*)&Bl[off];
        }
        __syncthreads();
        float c[2][4][4] = {};
        mma_chunk(c, sb, wm, wn, lane);
#pragma unroll
        for (int mt = 0; mt < 2; mt++)
#pragma unroll
            for (int nt = 0; nt < 4; nt++) {
                int col = ct*64 + wn*32 + nt*8 + (lane & 3)*2;
                int r0 = wm*32 + mt*16 + (lane >> 2);
                int t0 = ts[r0], t1 = ts[r0 + 8];
                if (t0 >= 0) {
                    float g = gts[r0];
                    size_t base = ((size_t)(t0>>11)*NH + h)*NSEQ + (t0 & 2047);
                    *(float2*)&g_outh[base*DIMM + col] =
                        make_float2(c[mt][nt][0]*g, c[mt][nt][1]*g);
                }
                if (t1 >= 0) {
                    float g = gts[r0 + 8];
                    size_t base = ((size_t)(t1>>11)*NH + h)*NSEQ + (t1 & 2047);
                    *(float2*)&g_outh[base*DIMM + col] =
                        make_float2(c[mt][nt][2]*g, c[mt][nt][3]*g);
                }
            }
    }
}

// ---------------- kernel 7: sum over heads ----------------
__global__ void reduce_kernel(float* __restrict__ out) {
    int idx = blockIdx.x * blockDim.x + threadIdx.x;
    const int total = TTOK * (DIMM/4);
    const float4* ph = (const float4*)g_outh;
    float4* po = (float4*)out;
    for (; idx < total; idx += gridDim.x * blockDim.x) {
        int t = idx >> 8;
        int d4 = idx & 255;
        int b_ = t >> 11, n = t & 2047;
        float4 s = make_float4(0.f,0.f,0.f,0.f);
#pragma unroll
        for (int h = 0; h < NH; h++) {
            float4 v = ph[((size_t)(b_*NH + h)*NSEQ + n)*256 + d4];
            s.x += v.x; s.y += v.y; s.z += v.z; s.w += v.w;
        }
        po[idx] = s;
    }
}

// ---------------- launch ----------------
extern "C" void kernel_launch(void* const* d_in, const int* in_sizes, int n_in,
                              void* d_out, int out_size) {
    const float* x  = (const float*)d_in[0];
    const float* wq = (const float*)d_in[1];
    const float* wk = (const float*)d_in[2];
    const float* wg = (const float*)d_in[3];
    const float* ve = (const float*)d_in[4];
    const float* oe = (const float*)d_in[5];
    float* out = (float*)d_out;

    cudaFuncSetAttribute(attn_kernel,
                         cudaFuncAttributeMaxDynamicSharedMemorySize, ATTN2_SMEM);
    cudaFuncSetAttribute(projt_kernel,
                         cudaFuncAttributeMaxDynamicSharedMemorySize, TENS_SMEM);
    cudaFuncSetAttribute(valt_kernel,
                         cudaFuncAttributeMaxDynamicSharedMemorySize, TENS_SMEM);
    cudaFuncSetAttribute(outt_kernel,
                         cudaFuncAttributeMaxDynamicSharedMemorySize, TENS_SMEM);

    __nv_bfloat16 *xh, *xl, *wqh, *wql, *wkh, *wkl, *veh, *vel, *oeh, *oel;
    cudaGetSymbolAddress((void**)&xh,  g_xh);  cudaGetSymbolAddress((void**)&xl,  g_xl);
    cudaGetSymbolAddress((void**)&wqh, g_wqh); cudaGetSymbolAddress((void**)&wql, g_wql);
    cudaGetSymbolAddress((void**)&wkh, g_wkh); cudaGetSymbolAddress((void**)&wkl, g_wkl);
    cudaGetSymbolAddress((void**)&veh, g_veh); cudaGetSymbolAddress((void**)&vel, g_vel);
    cudaGetSymbolAddress((void**)&oeh, g_oeh); cudaGetSymbolAddress((void**)&oel, g_oel);

    init_kernel<<<1, 64>>>();
    split_kernel<<<(TTOK*DIMM/2 + 255)/256, 256>>>(x, xh, xl, TTOK*DIMM/2);
    split_kernel<<<(1024*512/2 + 255)/256, 256>>>(wq, wqh, wql, 1024*512/2);
    split_kernel<<<(1024*512/2 + 255)/256, 256>>>(wk, wkh, wkl, 1024*512/2);
    split_kernel<<<(64*DIMM*DH/2 + 255)/256, 256>>>(ve, veh, vel, 64*DIMM*DH/2);
    split_kernel<<<(64*DH*DIMM/2 + 255)/256, 256>>>(oe, oeh, oel, 64*DH*DIMM/2);

    projt_kernel<<<dim3(TTOK/128, 16), 256, TENS_SMEM>>>();
    glogit_kernel<<<dim3(TTOK/128, 8), 256>>>(x, wg);
    gate_kernel<<<(TTOK*NH)/256, 256>>>();
    valt_kernel<<<dim3(NH*NE, TTOK/128), 256, TENS_SMEM>>>();
    attn_kernel<<<dim3(BH, NSEQ/128), 256, ATTN2_SMEM>>>();
    outt_kernel<<<dim3(NH*NE, TTOK/128, DIMM/256), 256, TENS_SMEM>>>();
    reduce_kernel<<<2048, 256>>>(out);
}

// round 16
// speedup vs baseline: 1.0407x; 1.0407x over previous
#include <cuda_runtime.h>
#include <cuda_bf16.h>

#define BATCH 2
#define NSEQ  2048
#define DIMM  1024
#define NH    8
#define DH    64
#define NE    8
#define TTOK  (BATCH*NSEQ)     /* 4096 */
#define BH    (BATCH*NH)       /* 16 */
#define GCOLS (NH*NE)          /* 64 */

typedef unsigned long long ull;

// ---------------- warp-MMA helpers (sm_80+ PTX, works on sm_100 base) ----------------
__device__ __forceinline__ unsigned smem_u32(const void* p) {
    unsigned a;
    asm("{ .reg .u64 t; cvta.to.shared.u64 t, %1; cvt.u32.u64 %0, t; }" : "=r"(a) : "l"(p));
    return a;
}
__device__ __forceinline__ void ldsm_x4(unsigned& r0, unsigned& r1, unsigned& r2, unsigned& r3,
                                        unsigned addr) {
    asm volatile("ldmatrix.sync.aligned.m8n8.x4.shared.b16 {%0,%1,%2,%3}, [%4];"
                 : "=r"(r0), "=r"(r1), "=r"(r2), "=r"(r3) : "r"(addr));
}
__device__ __forceinline__ void ldsm_x2t(unsigned& r0, unsigned& r1, unsigned addr) {
    asm volatile("ldmatrix.sync.aligned.m8n8.x2.trans.shared.b16 {%0,%1}, [%2];"
                 : "=r"(r0), "=r"(r1) : "r"(addr));
}
__device__ __forceinline__ void mma_bf16(float* c,
                                         unsigned a0, unsigned a1, unsigned a2, unsigned a3,
                                         unsigned b0, unsigned b1) {
    asm volatile("mma.sync.aligned.m16n8k16.row.col.f32.bf16.bf16.f32 "
                 "{%0,%1,%2,%3}, {%4,%5,%6,%7}, {%8,%9}, {%0,%1,%2,%3};"
                 : "+f"(c[0]), "+f"(c[1]), "+f"(c[2]), "+f"(c[3])
                 : "r"(a0), "r"(a1), "r"(a2), "r"(a3), "r"(b0), "r"(b1));
}

// split fp32x8 into hi/lo bf16x8, store 16B each to smem (byte offsets)
__device__ __forceinline__ void split_store8(char* hi_base, char* lo_base, unsigned off,
                                             float4 v0, float4 v1) {
    float v[8] = {v0.x, v0.y, v0.z, v0.w, v1.x, v1.y, v1.z, v1.w};
    unsigned hw[4], lw[4];
#pragma unroll
    for (int p = 0; p < 4; p++) {
        __nv_bfloat16 b0 = __float2bfloat16_rn(v[2*p]);
        __nv_bfloat16 b1 = __float2bfloat16_rn(v[2*p+1]);
        __nv_bfloat162 hh = __halves2bfloat162(b0, b1);
        hw[p] = *(unsigned*)&hh;
        float l0 = v[2*p]   - __bfloat162float(b0);
        float l1 = v[2*p+1] - __bfloat162float(b1);
        __nv_bfloat162 ll = __floats2bfloat162_rn(l0, l1);
        lw[p] = *(unsigned*)&ll;
    }
    *(uint4*)(hi_base + off) = make_uint4(hw[0], hw[1], hw[2], hw[3]);
    *(uint4*)(lo_base + off) = make_uint4(lw[0], lw[1], lw[2], lw[3]);
}

// transposed scatter: element i goes to [(d0+i)*ld + row] (bf16 counts)
__device__ __forceinline__ void split_store8_T(char* hi_base, char* lo_base,
                                               int d0, int row, int ld,
                                               float4 v0, float4 v1) {
    float v[8] = {v0.x, v0.y, v0.z, v0.w, v1.x, v1.y, v1.z, v1.w};
#pragma unroll
    for (int i = 0; i < 8; i++) {
        __nv_bfloat16 h = __float2bfloat16_rn(v[i]);
        __nv_bfloat16 l = __float2bfloat16_rn(v[i] - __bfloat162float(h));
        *(__nv_bfloat16*)(hi_base + ((size_t)(d0+i)*ld + row)*2) = h;
        *(__nv_bfloat16*)(lo_base + ((size_t)(d0+i)*ld + row)*2) = l;
    }
}

// ---------------- scratch ----------------
static __device__ float g_q[BH*NSEQ*DH];
static __device__ float g_k[BH*NSEQ*DH];
static __device__ float g_gpart[8][TTOK*GCOLS];
static __device__ float g_gate[BH*NSEQ];
static __device__ int   g_cnt[NH*NE];
static __device__ int   g_list[NH*NE*TTOK];
static __device__ float g_vals[BH*NSEQ*DH];
static __device__ float g_attn[BH*NSEQ*DH];
static __device__ float g_outh[(size_t)BH*NSEQ*DIMM];

__global__ void init_kernel() {
    int i = threadIdx.x;
    if (i < NH*NE) g_cnt[i] = 0;
}

// ---------------- smem layout for GEMM-MMA kernels (bytes) ----------------
#define LDA   72
#define SM_TS   0
#define SM_GTS  512
#define SM_AHI  1024
#define SM_ALO  (SM_AHI + 128*LDA*2)
#define SM_BHI  (SM_ALO + 128*LDA*2)
#define SM_BLO  (SM_BHI + 64*LDA*2)
#define TENS_SMEM (SM_BLO + 64*LDA*2)   /* 56320 */

// warp compute over one 64-K chunk: 4 ksteps x (2m x 4n) x 3 split terms
__device__ __forceinline__ void mma_chunk(float c[2][4][4], unsigned sb,
                                          int wm, int wn, int lane) {
#pragma unroll
    for (int ks = 0; ks < 4; ks++) {
        int k0 = ks * 16;
        unsigned ah[2][4], al[2][4], bh[4][2], bl[4][2];
#pragma unroll
        for (int mt = 0; mt < 2; mt++) {
            int row = wm*32 + mt*16 + (lane & 15);
            unsigned off = (unsigned)(row*LDA + k0 + (lane >> 4)*8) * 2;
            ldsm_x4(ah[mt][0], ah[mt][1], ah[mt][2], ah[mt][3], sb + SM_AHI + off);
            ldsm_x4(al[mt][0], al[mt][1], al[mt][2], al[mt][3], sb + SM_ALO + off);
        }
#pragma unroll
        for (int nt = 0; nt < 4; nt++) {
            int n0 = wn*32 + nt*8;
            unsigned off = (unsigned)((k0 + (lane & 15))*LDA + n0) * 2;
            ldsm_x2t(bh[nt][0], bh[nt][1], sb + SM_BHI + off);
            ldsm_x2t(bl[nt][0], bl[nt][1], sb + SM_BLO + off);
        }
#pragma unroll
        for (int mt = 0; mt < 2; mt++)
#pragma unroll
            for (int nt = 0; nt < 4; nt++) {
                mma_bf16(c[mt][nt], ah[mt][0], ah[mt][1], ah[mt][2], ah[mt][3],
                         bh[nt][0], bh[nt][1]);
                mma_bf16(c[mt][nt], ah[mt][0], ah[mt][1], ah[mt][2], ah[mt][3],
                         bl[nt][0], bl[nt][1]);
                mma_bf16(c[mt][nt], al[mt][0], al[mt][1], al[mt][2], al[mt][3],
                         bh[nt][0], bh[nt][1]);
            }
    }
}

// ---------------- kernel 1: proj Q/K via warp MMA (bf16 3-term split) ----------------
__global__ void __launch_bounds__(256, 2)
projt_kernel(const float* __restrict__ x,
             const float* __restrict__ wq,
             const float* __restrict__ wk) {
    extern __shared__ __align__(128) char smem[];
    unsigned sb = smem_u32(smem);
    int tid = threadIdx.x, wid = tid >> 5, lane = tid & 31;
    int bm = blockIdx.x, bn = blockIdx.y;
    int wm = wid & 3, wn = wid >> 2;
    const float* W = (bn < 8) ? wq : wk;
    int colbase = (bn & 7) * 64;

    float c[2][4][4] = {};
    for (int ch = 0; ch < 16; ch++) {
        if (ch) __syncthreads();
#pragma unroll
        for (int r = 0; r < 4; r++) {
            int task = tid + 256*r;
            int row = task >> 3, kg = task & 7;
            const float* p = x + (size_t)(bm*128 + row)*DIMM + ch*64 + kg*8;
            split_store8(smem + SM_AHI, smem + SM_ALO,
                         (unsigned)(row*LDA + kg*8)*2,
                         *(const float4*)p, *(const float4*)(p + 4));
        }
#pragma unroll
        for (int r = 0; r < 2; r++) {
            int task = tid + 256*r;
            int krow = task >> 3, ng = task & 7;
            const float* p = W + (size_t)(ch*64 + krow)*512 + colbase + ng*8;
            split_store8(smem + SM_BHI, smem + SM_BLO,
                         (unsigned)(krow*LDA + ng*8)*2,
                         *(const float4*)p, *(const float4*)(p + 4));
        }
        __syncthreads();
        mma_chunk(c, sb, wm, wn, lane);
    }
#pragma unroll
    for (int mt = 0; mt < 2; mt++)
#pragma unroll
        for (int nt = 0; nt < 4; nt++) {
            int r0 = bm*128 + wm*32 + mt*16 + (lane >> 2);
            int col = bn*64 + wn*32 + nt*8 + (lane & 3)*2;
            int b0_ = r0 >> 11, n0_ = r0 & 2047;
            int b1_ = (r0+8) >> 11, n1_ = (r0+8) & 2047;
            float* d0;
            float* d1;
            if (col < 512) {
                d0 = &g_q[((size_t)(b0_*NH + (col >> 6))*NSEQ + n0_)*DH + (col & 63)];
                d1 = &g_q[((size_t)(b1_*NH + (col >> 6))*NSEQ + n1_)*DH + (col & 63)];
            } else {
                int c2 = col - 512;
                d0 = &g_k[((size_t)(b0_*NH + (c2 >> 6))*NSEQ + n0_)*DH + (c2 & 63)];
                d1 = &g_k[((size_t)(b1_*NH + (c2 >> 6))*NSEQ + n1_)*DH + (c2 & 63)];
            }
            *(float2*)d0 = make_float2(c[mt][nt][0], c[mt][nt][1]);
            *(float2*)d1 = make_float2(c[mt][nt][2], c[mt][nt][3]);
        }
}

// ---------------- kernel 2: fp32 gate logits (split-K, exact routing) ----------------
__global__ void glogit_kernel(const float* __restrict__ x, const float* __restrict__ wg) {
    __shared__ float As[16][132];
    __shared__ float Bs[16][68];
    int tid = threadIdx.x;
    int bm = blockIdx.x, kz = blockIdx.y;
    int ty = tid >> 4, tx = tid & 15;
    float acc[8][4] = {};
    for (int kc = 0; kc < 8; kc++) {
#pragma unroll
        for (int r = 0; r < 8; r++) {
            int idx = tid + 256*r;
            int tok = idx >> 4, k = idx & 15;
            As[k][tok] = x[(size_t)(bm*128 + tok)*DIMM + kz*128 + kc*16 + k];
        }
#pragma unroll
        for (int r = 0; r < 4; r++) {
            int idx = tid + 256*r;
            int k = idx >> 6, c2 = idx & 63;
            Bs[k][c2] = wg[(size_t)(kz*128 + kc*16 + k)*GCOLS + c2];
        }
        __syncthreads();
#pragma unroll
        for (int k = 0; k < 16; k++) {
            float a_[8], b_[4];
#pragma unroll
            for (int i = 0; i < 8; i++) a_[i] = As[k][ty*8 + i];
#pragma unroll
            for (int j = 0; j < 4; j++) b_[j] = Bs[k][tx*4 + j];
#pragma unroll
            for (int i = 0; i < 8; i++)
#pragma unroll
                for (int j = 0; j < 4; j++)
                    acc[i][j] += a_[i] * b_[j];
        }
        __syncthreads();
    }
#pragma unroll
    for (int i = 0; i < 8; i++)
#pragma unroll
        for (int j = 0; j < 4; j++)
            g_gpart[kz][(size_t)(bm*128 + ty*8 + i)*GCOLS + tx*4 + j] = acc[i][j];
}

// ---------------- kernel 3: gate sigmoid + argmax + bucket append ----------------
__global__ void gate_kernel() {
    int id = blockIdx.x * blockDim.x + threadIdx.x;
    if (id >= TTOK*NH) return;
    int t = id / NH, h = id % NH;
    float lg[NE] = {};
#pragma unroll
    for (int kz = 0; kz < 8; kz++) {
        const float* gp = &g_gpart[kz][(size_t)t*GCOLS + h*NE];
        float4 a = *(const float4*)gp, b = *(const float4*)(gp + 4);
        lg[0]+=a.x; lg[1]+=a.y; lg[2]+=a.z; lg[3]+=a.w;
        lg[4]+=b.x; lg[5]+=b.y; lg[6]+=b.z; lg[7]+=b.w;
    }
    float best = lg[0]; int be = 0;
#pragma unroll
    for (int e = 1; e < NE; e++) { if (lg[e] > best) { best = lg[e]; be = e; } }
    float gate = 1.f / (1.f + __expf(-best));
    int b_ = t >> 11, n = t & 2047;
    g_gate[(size_t)(b_*NH + h)*NSEQ + n] = gate;
    int pos = atomicAdd(&g_cnt[h*NE + be], 1);
    g_list[(size_t)(h*NE + be)*TTOK + pos] = t;
}

// ---------------- kernel 4: value-expert GEMM via warp MMA ----------------
__global__ void __launch_bounds__(256, 2)
valt_kernel(const float* __restrict__ x, const float* __restrict__ vexp) {
    extern __shared__ __align__(128) char smem[];
    int he = blockIdx.x; int h = he >> 3, e = he & 7;
    int cnt = g_cnt[he];
    int start = blockIdx.y * 128;
    if (start >= cnt) return;
    unsigned sb = smem_u32(smem);
    int tid = threadIdx.x, wid = tid >> 5, lane = tid & 31;
    int wm = wid & 3, wn = wid >> 2;
    int* ts = (int*)(smem + SM_TS);
    float* gts = (float*)(smem + SM_GTS);
    if (tid < 128) {
        int t = (start + tid < cnt) ? g_list[(size_t)he*TTOK + start + tid] : -1;
        ts[tid] = t;
        gts[tid] = (t >= 0) ? g_gate[(size_t)((t>>11)*NH + h)*NSEQ + (t & 2047)] : 0.f;
    }
    __syncthreads();
    const float* B = vexp + (size_t)(e*NH + h)*DIMM*DH;

    float c[2][4][4] = {};
    for (int ch = 0; ch < 16; ch++) {
        if (ch) __syncthreads();
#pragma unroll
        for (int r = 0; r < 4; r++) {
            int task = tid + 256*r;
            int row = task >> 3, kg = task & 7;
            int t = ts[row];
            float4 v0 = make_float4(0.f,0.f,0.f,0.f), v1 = v0;
            if (t >= 0) {
                const float* p = x + (size_t)t*DIMM + ch*64 + kg*8;
                v0 = *(const float4*)p; v1 = *(const float4*)(p + 4);
                float g = gts[row];
                v0.x*=g; v0.y*=g; v0.z*=g; v0.w*=g;
                v1.x*=g; v1.y*=g; v1.z*=g; v1.w*=g;
            }
            split_store8(smem + SM_AHI, smem + SM_ALO,
                         (unsigned)(row*LDA + kg*8)*2, v0, v1);
        }
#pragma unroll
        for (int r = 0; r < 2; r++) {
            int task = tid + 256*r;
            int krow = task >> 3, ng = task & 7;
            const float* p = B + (size_t)(ch*64 + krow)*DH + ng*8;
            split_store8(smem + SM_BHI, smem + SM_BLO,
                         (unsigned)(krow*LDA + ng*8)*2,
                         *(const float4*)p, *(const float4*)(p + 4));
        }
        __syncthreads();
        mma_chunk(c, sb, wm, wn, lane);
    }
#pragma unroll
    for (int mt = 0; mt < 2; mt++)
#pragma unroll
        for (int nt = 0; nt < 4; nt++) {
            int col = wn*32 + nt*8 + (lane & 3)*2;
            int r0 = wm*32 + mt*16 + (lane >> 2);
            int t0 = ts[r0], t1 = ts[r0 + 8];
            if (t0 >= 0) {
                size_t base = ((size_t)(t0>>11)*NH + h)*NSEQ + (t0 & 2047);
                *(float2*)&g_vals[base*DH + col] = make_float2(c[mt][nt][0], c[mt][nt][1]);
            }
            if (t1 >= 0) {
                size_t base = ((size_t)(t1>>11)*NH + h)*NSEQ + (t1 & 2047);
                *(float2*)&g_vals[base*DH + col] = make_float2(c[mt][nt][2], c[mt][nt][3]);
            }
        }
}

// ---------------- kernel 5: causal flash attention via warp MMA ----------------
#define LDQT 136
#define LDP  72
#define LDPS 68
#define AT_QTH 0
#define AT_QTL (AT_QTH + 64*LDQT*2)
#define AT_KH  (AT_QTL + 64*LDQT*2)
#define AT_KL  (AT_KH + 64*LDP*2)
#define AT_VH  (AT_KL + 64*LDP*2)
#define AT_VL  (AT_VH + 64*LDP*2)
#define AT_PH  (AT_VL + 64*LDP*2)
#define AT_PL  (AT_PH + 128*LDP*2)
#define AT_PS  (AT_PL + 128*LDP*2)
#define AT_M   (AT_PS + 128*LDPS*4)
#define AT_L   (AT_M + 512)
#define AT_F   (AT_L + 512)
#define ATTN2_SMEM (AT_F + 512)          /* 144896 */

__global__ void __launch_bounds__(256, 1)
attn_kernel() {
    extern __shared__ __align__(128) char smem[];
    unsigned sb = smem_u32(smem);
    float* Ps  = (float*)(smem + AT_PS);
    float* m_s = (float*)(smem + AT_M);
    float* l_s = (float*)(smem + AT_L);
    float* f_s = (float*)(smem + AT_F);
    int bh = blockIdx.x;
    int qt = (int)(gridDim.y - 1) - (int)blockIdx.y;   // heavy tiles first
    int qbase = qt * 128;
    int tid = threadIdx.x, wid = tid >> 5, lane = tid & 31;
    int wm = wid & 3, wn = wid >> 2;       // O tiling: 4m x 2n
    int wmS = wid & 1, wnS = wid >> 1;     // S^T tiling: 2m(kv) x 4n(q)
    const float scale = 0.125f;

    // stage Q^T split (scaled), one time: [d][qrow]
#pragma unroll
    for (int r = 0; r < 4; r++) {
        int task = tid + 256*r;
        int row = task >> 3, d0 = (task & 7)*8;
        const float* p = &g_q[((size_t)bh*NSEQ + qbase + row)*DH + d0];
        float4 v0 = *(const float4*)p, v1 = *(const float4*)(p + 4);
        v0.x*=scale; v0.y*=scale; v0.z*=scale; v0.w*=scale;
        v1.x*=scale; v1.y*=scale; v1.z*=scale; v1.w*=scale;
        split_store8_T(smem + AT_QTH, smem + AT_QTL, d0, row, LDQT, v0, v1);
    }
    if (tid < 128) { m_s[tid] = -1e30f; l_s[tid] = 0.f; }

    float o[2][4][4] = {};
    int ntiles = qt*2 + 2;
    for (int jt = 0; jt < ntiles; jt++) {
        __syncthreads();
        // stage K,V tiles (natural [kv][d], split)
#pragma unroll
        for (int r = 0; r < 2; r++) {
            int task = tid + 256*r;
            int j = task >> 3, d0 = (task & 7)*8;
            const float* pk = &g_k[((size_t)bh*NSEQ + jt*64 + j)*DH + d0];
            split_store8(smem + AT_KH, smem + AT_KL, (unsigned)(j*LDP + d0)*2,
                         *(const float4*)pk, *(const float4*)(pk + 4));
            const float* pv = &g_vals[((size_t)bh*NSEQ + jt*64 + j)*DH + d0];
            split_store8(smem + AT_VH, smem + AT_VL, (unsigned)(j*LDP + d0)*2,
                         *(const float4*)pv, *(const float4*)(pv + 4));
        }
        __syncthreads();
        // S^T mma: A=K [kv][d], B=Q^T [d][q]
        float s[2][4][4] = {};
#pragma unroll
        for (int ks = 0; ks < 4; ks++) {
            int k0 = ks * 16;
            unsigned ah[2][4], al[2][4], bh2[4][2], bl2[4][2];
#pragma unroll
            for (int mt = 0; mt < 2; mt++) {
                int row = wmS*32 + mt*16 + (lane & 15);
                unsigned off = (unsigned)(row*LDP + k0 + (lane >> 4)*8) * 2;
                ldsm_x4(ah[mt][0], ah[mt][1], ah[mt][2], ah[mt][3], sb + AT_KH + off);
                ldsm_x4(al[mt][0], al[mt][1], al[mt][2], al[mt][3], sb + AT_KL + off);
            }
#pragma unroll
            for (int nt = 0; nt < 4; nt++) {
                int n0 = wnS*32 + nt*8;
                unsigned off = (unsigned)((k0 + (lane & 15))*LDQT + n0) * 2;
                ldsm_x2t(bh2[nt][0], bh2[nt][1], sb + AT_QTH + off);
                ldsm_x2t(bl2[nt][0], bl2[nt][1], sb + AT_QTL + off);
            }
#pragma unroll
            for (int mt = 0; mt < 2; mt++)
#pragma unroll
                for (int nt = 0; nt < 4; nt++) {
                    mma_bf16(s[mt][nt], ah[mt][0], ah[mt][1], ah[mt][2], ah[mt][3],
                             bh2[nt][0], bh2[nt][1]);
                    mma_bf16(s[mt][nt], ah[mt][0], ah[mt][1], ah[mt][2], ah[mt][3],
                             bl2[nt][0], bl2[nt][1]);
                    mma_bf16(s[mt][nt], al[mt][0], al[mt][1], al[mt][2], al[mt][3],
                             bh2[nt][0], bh2[nt][1]);
                }
        }
        // causal mask + store S^T -> Ps[q][kv]
        bool diag = (jt*64 + 63 > qbase);
#pragma unroll
        for (int mt = 0; mt < 2; mt++)
#pragma unroll
            for (int nt = 0; nt < 4; nt++) {
                int kvr = wmS*32 + mt*16 + (lane >> 2);
                int q0  = wnS*32 + nt*8 + (lane & 3)*2;
                if (diag) {
                    int kg = jt*64 + kvr, qg = qbase + q0;
                    if (kg > qg)       s[mt][nt][0] = -1e30f;
                    if (kg > qg+1)     s[mt][nt][1] = -1e30f;
                    if (kg+8 > qg)     s[mt][nt][2] = -1e30f;
                    if (kg+8 > qg+1)   s[mt][nt][3] = -1e30f;
                }
                Ps[q0*LDPS + kvr]       = s[mt][nt][0];
                Ps[(q0+1)*LDPS + kvr]   = s[mt][nt][1];
                Ps[q0*LDPS + kvr+8]     = s[mt][nt][2];
                Ps[(q0+1)*LDPS + kvr+8] = s[mt][nt][3];
            }
        __syncthreads();
        // online softmax (2 thr/row) + emit P as split bf16 [q][kv]
        {
            int row = tid >> 1, half = tid & 1;
            float* P = &Ps[row*LDPS + half*32];
            float mx = m_s[row];
#pragma unroll 8
            for (int j2 = 0; j2 < 32; j2++) mx = fmaxf(mx, P[j2]);
            mx = fmaxf(mx, __shfl_xor_sync(0xffffffffu, mx, 1));
            float sum = 0.f;
            __nv_bfloat162* PH2 = (__nv_bfloat162*)(smem + AT_PH + (size_t)(row*LDP + half*32)*2);
            __nv_bfloat162* PL2 = (__nv_bfloat162*)(smem + AT_PL + (size_t)(row*LDP + half*32)*2);
#pragma unroll 4
            for (int j2 = 0; j2 < 32; j2 += 2) {
                float p0 = __expf(P[j2] - mx);
                float p1 = __expf(P[j2+1] - mx);
                sum += p0 + p1;
                __nv_bfloat16 h0 = __float2bfloat16_rn(p0);
                __nv_bfloat16 h1 = __float2bfloat16_rn(p1);
                PH2[j2 >> 1] = __halves2bfloat162(h0, h1);
                PL2[j2 >> 1] = __floats2bfloat162_rn(p0 - __bfloat162float(h0),
                                                     p1 - __bfloat162float(h1));
            }
            sum += __shfl_xor_sync(0xffffffffu, sum, 1);
            if (half == 0) {
                float mo = m_s[row];
                float f = __expf(mo - mx);
                m_s[row] = mx;
                l_s[row] = l_s[row]*f + sum;
                f_s[row] = f;
            }
        }
        __syncthreads();
        // rescale O and accumulate P·V
#pragma unroll
        for (int mt = 0; mt < 2; mt++) {
            int r0 = wm*32 + mt*16 + (lane >> 2);
            float f0 = f_s[r0], f1 = f_s[r0 + 8];
#pragma unroll
            for (int nt = 0; nt < 4; nt++) {
                o[mt][nt][0] *= f0; o[mt][nt][1] *= f0;
                o[mt][nt][2] *= f1; o[mt][nt][3] *= f1;
            }
        }
#pragma unroll
        for (int ks = 0; ks < 4; ks++) {
            int k0 = ks * 16;
            unsigned ah[2][4], al[2][4], bh2[4][2], bl2[4][2];
#pragma unroll
            for (int mt = 0; mt < 2; mt++) {
                int row = wm*32 + mt*16 + (lane & 15);
                unsigned off = (unsigned)(row*LDP + k0 + (lane >> 4)*8) * 2;
                ldsm_x4(ah[mt][0], ah[mt][1], ah[mt][2], ah[mt][3], sb + AT_PH + off);
                ldsm_x4(al[mt][0], al[mt][1], al[mt][2], al[mt][3], sb + AT_PL + off);
            }
#pragma unroll
            for (int nt = 0; nt < 4; nt++) {
                int n0 = wn*32 + nt*8;
                unsigned off = (unsigned)((k0 + (lane & 15))*LDP + n0) * 2;
                ldsm_x2t(bh2[nt][0], bh2[nt][1], sb + AT_VH + off);
                ldsm_x2t(bl2[nt][0], bl2[nt][1], sb + AT_VL + off);
            }
#pragma unroll
            for (int mt = 0; mt < 2; mt++)
#pragma unroll
                for (int nt = 0; nt < 4; nt++) {
                    mma_bf16(o[mt][nt], ah[mt][0], ah[mt][1], ah[mt][2], ah[mt][3],
                             bh2[nt][0], bh2[nt][1]);
                    mma_bf16(o[mt][nt], ah[mt][0], ah[mt][1], ah[mt][2], ah[mt][3],
                             bl2[nt][0], bl2[nt][1]);
                    mma_bf16(o[mt][nt], al[mt][0], al[mt][1], al[mt][2], al[mt][3],
                             bh2[nt][0], bh2[nt][1]);
                }
        }
    }
    // epilogue: divide by l, write
#pragma unroll
    for (int mt = 0; mt < 2; mt++) {
        int r0 = wm*32 + mt*16 + (lane >> 2);
        float inv0 = 1.f / l_s[r0], inv1 = 1.f / l_s[r0 + 8];
#pragma unroll
        for (int nt = 0; nt < 4; nt++) {
            int col = wn*32 + nt*8 + (lane & 3)*2;
            *(float2*)&g_attn[((size_t)bh*NSEQ + qbase + r0)*DH + col] =
                make_float2(o[mt][nt][0]*inv0, o[mt][nt][1]*inv0);
            *(float2*)&g_attn[((size_t)bh*NSEQ + qbase + r0 + 8)*DH + col] =
                make_float2(o[mt][nt][2]*inv1, o[mt][nt][3]*inv1);
        }
    }
}

// ---------------- kernel 6: output-expert GEMM via warp MMA, 4 col-tiles/block ----------------
__global__ void __launch_bounds__(256, 2)
outt_kernel(const float* __restrict__ oexp) {
    extern __shared__ __align__(128) char smem[];
    int he = blockIdx.x; int h = he >> 3, e = he & 7;
    int cnt = g_cnt[he];
    int start = blockIdx.y * 128;
    if (start >= cnt) return;
    int ct0 = blockIdx.z * 4;            // 4 blocks x 4 tiles of 64 cols
    unsigned sb = smem_u32(smem);
    int tid = threadIdx.x, wid = tid >> 5, lane = tid & 31;
    int wm = wid & 3, wn = wid >> 2;
    int* ts = (int*)(smem + SM_TS);
    float* gts = (float*)(smem + SM_GTS);
    if (tid < 128) {
        int t = (start + tid < cnt) ? g_list[(size_t)he*TTOK + start + tid] : -1;
        ts[tid] = t;
        gts[tid] = (t >= 0) ? g_gate[(size_t)((t>>11)*NH + h)*NSEQ + (t & 2047)] : 0.f;
    }
    __syncthreads();
    const float* B = oexp + (size_t)(e*NH + h)*DH*DIMM;

    // stage A once (gated attn [128 tok][64 dh])
#pragma unroll
    for (int r = 0; r < 4; r++) {
        int task = tid + 256*r;
        int row = task >> 3, kg = task & 7;
        int t = ts[row];
        float4 v0 = make_float4(0.f,0.f,0.f,0.f), v1 = v0;
        if (t >= 0) {
            size_t base = ((size_t)(t>>11)*NH + h)*NSEQ + (t & 2047);
            const float* p = &g_attn[base*DH + kg*8];
            v0 = *(const float4*)p; v1 = *(const float4*)(p + 4);
            float g = gts[row];
            v0.x*=g; v0.y*=g; v0.z*=g; v0.w*=g;
            v1.x*=g; v1.y*=g; v1.z*=g; v1.w*=g;
        }
        split_store8(smem + SM_AHI, smem + SM_ALO, (unsigned)(row*LDA + kg*8)*2, v0, v1);
    }

    for (int i = 0; i < 4; i++) {
        int ct = ct0 + i;
        __syncthreads();                 // A visible / previous B consumed
#pragma unroll
        for (int r = 0; r < 2; r++) {
            int task = tid + 256*r;
            int krow = task >> 3, ng = task & 7;
            const float* p = B + (size_t)krow*DIMM + ct*64 + ng*8;
            split_store8(smem + SM_BHI, smem + SM_BLO, (unsigned)(krow*LDA + ng*8)*2,
                         *(const float4*)p, *(const float4*)(p + 4));
        }
        __syncthreads();
        float c[2][4][4] = {};
        mma_chunk(c, sb, wm, wn, lane);
#pragma unroll
        for (int mt = 0; mt < 2; mt++)
#pragma unroll
            for (int nt = 0; nt < 4; nt++) {
                int col = ct*64 + wn*32 + nt*8 + (lane & 3)*2;
                int r0 = wm*32 + mt*16 + (lane >> 2);
                int t0 = ts[r0], t1 = ts[r0 + 8];
                if (t0 >= 0) {
                    size_t base = ((size_t)(t0>>11)*NH + h)*NSEQ + (t0 & 2047);
                    *(float2*)&g_outh[base*DIMM + col] = make_float2(c[mt][nt][0], c[mt][nt][1]);
                }
                if (t1 >= 0) {
                    size_t base = ((size_t)(t1>>11)*NH + h)*NSEQ + (t1 & 2047);
                    *(float2*)&g_outh[base*DIMM + col] = make_float2(c[mt][nt][2], c[mt][nt][3]);
                }
            }
    }
}

// ---------------- kernel 7: sum over heads ----------------
__global__ void reduce_kernel(float* __restrict__ out) {
    int idx = blockIdx.x * blockDim.x + threadIdx.x;
    const int total = TTOK * (DIMM/4);
    const float4* ph = (const float4*)g_outh;
    float4* po = (float4*)out;
    for (; idx < total; idx += gridDim.x * blockDim.x) {
        int t = idx >> 8;
        int d4 = idx & 255;
        int b_ = t >> 11, n = t & 2047;
        float4 s = make_float4(0.f,0.f,0.f,0.f);
#pragma unroll
        for (int h = 0; h < NH; h++) {
            float4 v = ph[((size_t)(b_*NH + h)*NSEQ + n)*256 + d4];
            s.x += v.x; s.y += v.y; s.z += v.z; s.w += v.w;
        }
        po[idx] = s;
    }
}

// ---------------- launch (reordered: projt is 4th launch -> ncu capture slot) ----------------
extern "C" void kernel_launch(void* const* d_in, const int* in_sizes, int n_in,
                              void* d_out, int out_size) {
    const float* x  = (const float*)d_in[0];
    const float* wq = (const float*)d_in[1];
    const float* wk = (const float*)d_in[2];
    const float* wg = (const float*)d_in[3];
    const float* ve = (const float*)d_in[4];
    const float* oe = (const float*)d_in[5];
    float* out = (float*)d_out;

    cudaFuncSetAttribute(attn_kernel,
                         cudaFuncAttributeMaxDynamicSharedMemorySize, ATTN2_SMEM);
    cudaFuncSetAttribute(projt_kernel,
                         cudaFuncAttributeMaxDynamicSharedMemorySize, TENS_SMEM);
    cudaFuncSetAttribute(valt_kernel,
                         cudaFuncAttributeMaxDynamicSharedMemorySize, TENS_SMEM);
    cudaFuncSetAttribute(outt_kernel,
                         cudaFuncAttributeMaxDynamicSharedMemorySize, TENS_SMEM);

    init_kernel<<<1, 64>>>();
    glogit_kernel<<<dim3(TTOK/128, 8), 256>>>(x, wg);
    gate_kernel<<<(TTOK*NH)/256, 256>>>();
    projt_kernel<<<dim3(TTOK/128, 16), 256, TENS_SMEM>>>(x, wq, wk);
    valt_kernel<<<dim3(NH*NE, TTOK/128), 256, TENS_SMEM>>>(x, ve);
    attn_kernel<<<dim3(BH, NSEQ/128), 256, ATTN2_SMEM>>>();
    outt_kernel<<<dim3(NH*NE, TTOK/128, DIMM/256), 256, TENS_SMEM>>>(oe);
    reduce_kernel<<<2048, 256>>>(out);
}

// round 17
// speedup vs baseline: 1.0550x; 1.0138x over previous
#include <cuda_runtime.h>
#include <cuda_bf16.h>

#define BATCH 2
#define NSEQ  2048
#define DIMM  1024
#define NH    8
#define DH    64
#define NE    8
#define TTOK  (BATCH*NSEQ)     /* 4096 */
#define BH    (BATCH*NH)       /* 16 */
#define GCOLS (NH*NE)          /* 64 */

typedef unsigned long long ull;

// ---------------- warp-MMA helpers (sm_80+ PTX, works on sm_100 base) ----------------
__device__ __forceinline__ unsigned smem_u32(const void* p) {
    unsigned a;
    asm("{ .reg .u64 t; cvta.to.shared.u64 t, %1; cvt.u32.u64 %0, t; }" : "=r"(a) : "l"(p));
    return a;
}
__device__ __forceinline__ void ldsm_x4(unsigned& r0, unsigned& r1, unsigned& r2, unsigned& r3,
                                        unsigned addr) {
    asm volatile("ldmatrix.sync.aligned.m8n8.x4.shared.b16 {%0,%1,%2,%3}, [%4];"
                 : "=r"(r0), "=r"(r1), "=r"(r2), "=r"(r3) : "r"(addr));
}
// x4 transposed: four 8x8 tiles; lane groups of 8 give row addresses.
// Use for B-side: covers k0..k0+15 x n0..n0+15 (two adjacent 8-col frag tiles).
__device__ __forceinline__ void ldsm_x4t(unsigned& r0, unsigned& r1, unsigned& r2, unsigned& r3,
                                         unsigned addr) {
    asm volatile("ldmatrix.sync.aligned.m8n8.x4.trans.shared.b16 {%0,%1,%2,%3}, [%4];"
                 : "=r"(r0), "=r"(r1), "=r"(r2), "=r"(r3) : "r"(addr));
}
__device__ __forceinline__ void mma_bf16(float* c,
                                         unsigned a0, unsigned a1, unsigned a2, unsigned a3,
                                         unsigned b0, unsigned b1) {
    asm volatile("mma.sync.aligned.m16n8k16.row.col.f32.bf16.bf16.f32 "
                 "{%0,%1,%2,%3}, {%4,%5,%6,%7}, {%8,%9}, {%0,%1,%2,%3};"
                 : "+f"(c[0]), "+f"(c[1]), "+f"(c[2]), "+f"(c[3])
                 : "r"(a0), "r"(a1), "r"(a2), "r"(a3), "r"(b0), "r"(b1));
}

// B-side x4t address: k rows, n cols, LD in bf16 elements; returns byte offset
__device__ __forceinline__ unsigned bx4t_off(int k0, int n0, int ld, int lane) {
    return (unsigned)((k0 + (lane & 7) + ((lane >> 3) & 1)*8)*ld + n0 + (lane >> 4)*8) * 2;
}

// split fp32x8 into hi/lo bf16x8, store 16B each to smem (byte offsets)
__device__ __forceinline__ void split_store8(char* hi_base, char* lo_base, unsigned off,
                                             float4 v0, float4 v1) {
    float v[8] = {v0.x, v0.y, v0.z, v0.w, v1.x, v1.y, v1.z, v1.w};
    unsigned hw[4], lw[4];
#pragma unroll
    for (int p = 0; p < 4; p++) {
        __nv_bfloat16 b0 = __float2bfloat16_rn(v[2*p]);
        __nv_bfloat16 b1 = __float2bfloat16_rn(v[2*p+1]);
        __nv_bfloat162 hh = __halves2bfloat162(b0, b1);
        hw[p] = *(unsigned*)&hh;
        float l0 = v[2*p]   - __bfloat162float(b0);
        float l1 = v[2*p+1] - __bfloat162float(b1);
        __nv_bfloat162 ll = __floats2bfloat162_rn(l0, l1);
        lw[p] = *(unsigned*)&ll;
    }
    *(uint4*)(hi_base + off) = make_uint4(hw[0], hw[1], hw[2], hw[3]);
    *(uint4*)(lo_base + off) = make_uint4(lw[0], lw[1], lw[2], lw[3]);
}

// transposed scatter: element i goes to [(d0+i)*ld + row] (bf16 counts)
__device__ __forceinline__ void split_store8_T(char* hi_base, char* lo_base,
                                               int d0, int row, int ld,
                                               float4 v0, float4 v1) {
    float v[8] = {v0.x, v0.y, v0.z, v0.w, v1.x, v1.y, v1.z, v1.w};
#pragma unroll
    for (int i = 0; i < 8; i++) {
        __nv_bfloat16 h = __float2bfloat16_rn(v[i]);
        __nv_bfloat16 l = __float2bfloat16_rn(v[i] - __bfloat162float(h));
        *(__nv_bfloat16*)(hi_base + ((size_t)(d0+i)*ld + row)*2) = h;
        *(__nv_bfloat16*)(lo_base + ((size_t)(d0+i)*ld + row)*2) = l;
    }
}

// ---------------- scratch ----------------
static __device__ float g_q[BH*NSEQ*DH];
static __device__ float g_k[BH*NSEQ*DH];
static __device__ float g_gpart[8][TTOK*GCOLS];
static __device__ float g_gate[BH*NSEQ];
static __device__ int   g_cnt[NH*NE];
static __device__ int   g_list[NH*NE*TTOK];
static __device__ float g_vals[BH*NSEQ*DH];
static __device__ float g_attn[BH*NSEQ*DH];
static __device__ float g_outh[(size_t)BH*NSEQ*DIMM];

__global__ void init_kernel() {
    int i = threadIdx.x;
    if (i < NH*NE) g_cnt[i] = 0;
}

// ---------------- smem layout for GEMM-MMA kernels (bytes) ----------------
#define LDA   72
#define SM_TS   0
#define SM_GTS  512
#define SM_AHI  1024
#define SM_ALO  (SM_AHI + 128*LDA*2)
#define SM_BHI  (SM_ALO + 128*LDA*2)
#define SM_BLO  (SM_BHI + 64*LDA*2)
#define TENS_SMEM (SM_BLO + 64*LDA*2)   /* 56320 */

// warp compute over one 64-K chunk: 4 ksteps x (2m x 4n) x 3 split terms
__device__ __forceinline__ void mma_chunk(float c[2][4][4], unsigned sb,
                                          int wm, int wn, int lane) {
#pragma unroll
    for (int ks = 0; ks < 4; ks++) {
        int k0 = ks * 16;
        unsigned ah[2][4], al[2][4], bh[4][2], bl[4][2];
#pragma unroll
        for (int mt = 0; mt < 2; mt++) {
            int row = wm*32 + mt*16 + (lane & 15);
            unsigned off = (unsigned)(row*LDA + k0 + (lane >> 4)*8) * 2;
            ldsm_x4(ah[mt][0], ah[mt][1], ah[mt][2], ah[mt][3], sb + SM_AHI + off);
            ldsm_x4(al[mt][0], al[mt][1], al[mt][2], al[mt][3], sb + SM_ALO + off);
        }
#pragma unroll
        for (int np = 0; np < 2; np++) {
            int n0 = wn*32 + np*16;
            unsigned off = bx4t_off(k0, n0, LDA, lane);
            ldsm_x4t(bh[2*np][0], bh[2*np][1], bh[2*np+1][0], bh[2*np+1][1],
                     sb + SM_BHI + off);
            ldsm_x4t(bl[2*np][0], bl[2*np][1], bl[2*np+1][0], bl[2*np+1][1],
                     sb + SM_BLO + off);
        }
#pragma unroll
        for (int mt = 0; mt < 2; mt++)
#pragma unroll
            for (int nt = 0; nt < 4; nt++) {
                mma_bf16(c[mt][nt], ah[mt][0], ah[mt][1], ah[mt][2], ah[mt][3],
                         bh[nt][0], bh[nt][1]);
                mma_bf16(c[mt][nt], ah[mt][0], ah[mt][1], ah[mt][2], ah[mt][3],
                         bl[nt][0], bl[nt][1]);
                mma_bf16(c[mt][nt], al[mt][0], al[mt][1], al[mt][2], al[mt][3],
                         bh[nt][0], bh[nt][1]);
            }
    }
}

// ---------------- kernel 1: proj Q/K via warp MMA (bf16 3-term split) ----------------
__global__ void __launch_bounds__(256, 2)
projt_kernel(const float* __restrict__ x,
             const float* __restrict__ wq,
             const float* __restrict__ wk) {
    extern __shared__ __align__(128) char smem[];
    unsigned sb = smem_u32(smem);
    int tid = threadIdx.x, wid = tid >> 5, lane = tid & 31;
    int bm = blockIdx.x, bn = blockIdx.y;
    int wm = wid & 3, wn = wid >> 2;
    const float* W = (bn < 8) ? wq : wk;
    int colbase = (bn & 7) * 64;

    float c[2][4][4] = {};
    for (int ch = 0; ch < 16; ch++) {
        if (ch) __syncthreads();
#pragma unroll
        for (int r = 0; r < 4; r++) {
            int task = tid + 256*r;
            int row = task >> 3, kg = task & 7;
            const float* p = x + (size_t)(bm*128 + row)*DIMM + ch*64 + kg*8;
            split_store8(smem + SM_AHI, smem + SM_ALO,
                         (unsigned)(row*LDA + kg*8)*2,
                         *(const float4*)p, *(const float4*)(p + 4));
        }
#pragma unroll
        for (int r = 0; r < 2; r++) {
            int task = tid + 256*r;
            int krow = task >> 3, ng = task & 7;
            const float* p = W + (size_t)(ch*64 + krow)*512 + colbase + ng*8;
            split_store8(smem + SM_BHI, smem + SM_BLO,
                         (unsigned)(krow*LDA + ng*8)*2,
                         *(const float4*)p, *(const float4*)(p + 4));
        }
        __syncthreads();
        mma_chunk(c, sb, wm, wn, lane);
    }
#pragma unroll
    for (int mt = 0; mt < 2; mt++)
#pragma unroll
        for (int nt = 0; nt < 4; nt++) {
            int r0 = bm*128 + wm*32 + mt*16 + (lane >> 2);
            int col = bn*64 + wn*32 + nt*8 + (lane & 3)*2;
            int b0_ = r0 >> 11, n0_ = r0 & 2047;
            int b1_ = (r0+8) >> 11, n1_ = (r0+8) & 2047;
            float* d0;
            float* d1;
            if (col < 512) {
                d0 = &g_q[((size_t)(b0_*NH + (col >> 6))*NSEQ + n0_)*DH + (col & 63)];
                d1 = &g_q[((size_t)(b1_*NH + (col >> 6))*NSEQ + n1_)*DH + (col & 63)];
            } else {
                int c2 = col - 512;
                d0 = &g_k[((size_t)(b0_*NH + (c2 >> 6))*NSEQ + n0_)*DH + (c2 & 63)];
                d1 = &g_k[((size_t)(b1_*NH + (c2 >> 6))*NSEQ + n1_)*DH + (c2 & 63)];
            }
            *(float2*)d0 = make_float2(c[mt][nt][0], c[mt][nt][1]);
            *(float2*)d1 = make_float2(c[mt][nt][2], c[mt][nt][3]);
        }
}

// ---------------- kernel 2: fp32 gate logits (split-K, exact routing) ----------------
__global__ void glogit_kernel(const float* __restrict__ x, const float* __restrict__ wg) {
    __shared__ float As[16][132];
    __shared__ float Bs[16][68];
    int tid = threadIdx.x;
    int bm = blockIdx.x, kz = blockIdx.y;
    int ty = tid >> 4, tx = tid & 15;
    float acc[8][4] = {};
    for (int kc = 0; kc < 8; kc++) {
#pragma unroll
        for (int r = 0; r < 8; r++) {
            int idx = tid + 256*r;
            int tok = idx >> 4, k = idx & 15;
            As[k][tok] = x[(size_t)(bm*128 + tok)*DIMM + kz*128 + kc*16 + k];
        }
#pragma unroll
        for (int r = 0; r < 4; r++) {
            int idx = tid + 256*r;
            int k = idx >> 6, c2 = idx & 63;
            Bs[k][c2] = wg[(size_t)(kz*128 + kc*16 + k)*GCOLS + c2];
        }
        __syncthreads();
#pragma unroll
        for (int k = 0; k < 16; k++) {
            float a_[8], b_[4];
#pragma unroll
            for (int i = 0; i < 8; i++) a_[i] = As[k][ty*8 + i];
#pragma unroll
            for (int j = 0; j < 4; j++) b_[j] = Bs[k][tx*4 + j];
#pragma unroll
            for (int i = 0; i < 8; i++)
#pragma unroll
                for (int j = 0; j < 4; j++)
                    acc[i][j] += a_[i] * b_[j];
        }
        __syncthreads();
    }
#pragma unroll
    for (int i = 0; i < 8; i++)
#pragma unroll
        for (int j = 0; j < 4; j++)
            g_gpart[kz][(size_t)(bm*128 + ty*8 + i)*GCOLS + tx*4 + j] = acc[i][j];
}

// ---------------- kernel 3: gate sigmoid + argmax + bucket append ----------------
__global__ void gate_kernel() {
    int id = blockIdx.x * blockDim.x + threadIdx.x;
    if (id >= TTOK*NH) return;
    int t = id / NH, h = id % NH;
    float lg[NE] = {};
#pragma unroll
    for (int kz = 0; kz < 8; kz++) {
        const float* gp = &g_gpart[kz][(size_t)t*GCOLS + h*NE];
        float4 a = *(const float4*)gp, b = *(const float4*)(gp + 4);
        lg[0]+=a.x; lg[1]+=a.y; lg[2]+=a.z; lg[3]+=a.w;
        lg[4]+=b.x; lg[5]+=b.y; lg[6]+=b.z; lg[7]+=b.w;
    }
    float best = lg[0]; int be = 0;
#pragma unroll
    for (int e = 1; e < NE; e++) { if (lg[e] > best) { best = lg[e]; be = e; } }
    float gate = 1.f / (1.f + __expf(-best));
    int b_ = t >> 11, n = t & 2047;
    g_gate[(size_t)(b_*NH + h)*NSEQ + n] = gate;
    int pos = atomicAdd(&g_cnt[h*NE + be], 1);
    g_list[(size_t)(h*NE + be)*TTOK + pos] = t;
}

// ---------------- kernel 4: value-expert GEMM via warp MMA ----------------
__global__ void __launch_bounds__(256, 2)
valt_kernel(const float* __restrict__ x, const float* __restrict__ vexp) {
    extern __shared__ __align__(128) char smem[];
    int he = blockIdx.x; int h = he >> 3, e = he & 7;
    int cnt = g_cnt[he];
    int start = blockIdx.y * 128;
    if (start >= cnt) return;
    unsigned sb = smem_u32(smem);
    int tid = threadIdx.x, wid = tid >> 5, lane = tid & 31;
    int wm = wid & 3, wn = wid >> 2;
    int* ts = (int*)(smem + SM_TS);
    float* gts = (float*)(smem + SM_GTS);
    if (tid < 128) {
        int t = (start + tid < cnt) ? g_list[(size_t)he*TTOK + start + tid] : -1;
        ts[tid] = t;
        gts[tid] = (t >= 0) ? g_gate[(size_t)((t>>11)*NH + h)*NSEQ + (t & 2047)] : 0.f;
    }
    __syncthreads();
    const float* B = vexp + (size_t)(e*NH + h)*DIMM*DH;

    float c[2][4][4] = {};
    for (int ch = 0; ch < 16; ch++) {
        if (ch) __syncthreads();
#pragma unroll
        for (int r = 0; r < 4; r++) {
            int task = tid + 256*r;
            int row = task >> 3, kg = task & 7;
            int t = ts[row];
            float4 v0 = make_float4(0.f,0.f,0.f,0.f), v1 = v0;
            if (t >= 0) {
                const float* p = x + (size_t)t*DIMM + ch*64 + kg*8;
                v0 = *(const float4*)p; v1 = *(const float4*)(p + 4);
                float g = gts[row];
                v0.x*=g; v0.y*=g; v0.z*=g; v0.w*=g;
                v1.x*=g; v1.y*=g; v1.z*=g; v1.w*=g;
            }
            split_store8(smem + SM_AHI, smem + SM_ALO,
                         (unsigned)(row*LDA + kg*8)*2, v0, v1);
        }
#pragma unroll
        for (int r = 0; r < 2; r++) {
            int task = tid + 256*r;
            int krow = task >> 3, ng = task & 7;
            const float* p = B + (size_t)(ch*64 + krow)*DH + ng*8;
            split_store8(smem + SM_BHI, smem + SM_BLO,
                         (unsigned)(krow*LDA + ng*8)*2,
                         *(const float4*)p, *(const float4*)(p + 4));
        }
        __syncthreads();
        mma_chunk(c, sb, wm, wn, lane);
    }
#pragma unroll
    for (int mt = 0; mt < 2; mt++)
#pragma unroll
        for (int nt = 0; nt < 4; nt++) {
            int col = wn*32 + nt*8 + (lane & 3)*2;
            int r0 = wm*32 + mt*16 + (lane >> 2);
            int t0 = ts[r0], t1 = ts[r0 + 8];
            if (t0 >= 0) {
                size_t base = ((size_t)(t0>>11)*NH + h)*NSEQ + (t0 & 2047);
                *(float2*)&g_vals[base*DH + col] = make_float2(c[mt][nt][0], c[mt][nt][1]);
            }
            if (t1 >= 0) {
                size_t base = ((size_t)(t1>>11)*NH + h)*NSEQ + (t1 & 2047);
                *(float2*)&g_vals[base*DH + col] = make_float2(c[mt][nt][2], c[mt][nt][3]);
            }
        }
}

// ---------------- kernel 5: causal flash attention via warp MMA ----------------
#define LDQT 136
#define LDP  72
#define LDPS 68
#define AT_QTH 0
#define AT_QTL (AT_QTH + 64*LDQT*2)
#define AT_KH  (AT_QTL + 64*LDQT*2)
#define AT_KL  (AT_KH + 64*LDP*2)
#define AT_VH  (AT_KL + 64*LDP*2)
#define AT_VL  (AT_VH + 64*LDP*2)
#define AT_PH  (AT_VL + 64*LDP*2)
#define AT_PL  (AT_PH + 128*LDP*2)
#define AT_PS  (AT_PL + 128*LDP*2)
#define AT_M   (AT_PS + 128*LDPS*4)
#define AT_L   (AT_M + 512)
#define AT_F   (AT_L + 512)
#define ATTN2_SMEM (AT_F + 512)          /* 144896 */

__global__ void __launch_bounds__(256, 1)
attn_kernel() {
    extern __shared__ __align__(128) char smem[];
    unsigned sb = smem_u32(smem);
    float* Ps  = (float*)(smem + AT_PS);
    float* m_s = (float*)(smem + AT_M);
    float* l_s = (float*)(smem + AT_L);
    float* f_s = (float*)(smem + AT_F);
    int bh = blockIdx.x;
    int qt = (int)(gridDim.y - 1) - (int)blockIdx.y;   // heavy tiles first
    int qbase = qt * 128;
    int tid = threadIdx.x, wid = tid >> 5, lane = tid & 31;
    int wm = wid & 3, wn = wid >> 2;       // O tiling: 4m x 2n
    int wmS = wid & 1, wnS = wid >> 1;     // S^T tiling: 2m(kv) x 4n(q)
    const float scale = 0.125f;

    // stage Q^T split (scaled), one time: [d][qrow]
#pragma unroll
    for (int r = 0; r < 4; r++) {
        int task = tid + 256*r;
        int row = task >> 3, d0 = (task & 7)*8;
        const float* p = &g_q[((size_t)bh*NSEQ + qbase + row)*DH + d0];
        float4 v0 = *(const float4*)p, v1 = *(const float4*)(p + 4);
        v0.x*=scale; v0.y*=scale; v0.z*=scale; v0.w*=scale;
        v1.x*=scale; v1.y*=scale; v1.z*=scale; v1.w*=scale;
        split_store8_T(smem + AT_QTH, smem + AT_QTL, d0, row, LDQT, v0, v1);
    }
    if (tid < 128) { m_s[tid] = -1e30f; l_s[tid] = 0.f; }

    float o[2][4][4] = {};
    int ntiles = qt*2 + 2;
    for (int jt = 0; jt < ntiles; jt++) {
        __syncthreads();
        // stage K,V tiles (natural [kv][d], split)
#pragma unroll
        for (int r = 0; r < 2; r++) {
            int task = tid + 256*r;
            int j = task >> 3, d0 = (task & 7)*8;
            const float* pk = &g_k[((size_t)bh*NSEQ + jt*64 + j)*DH + d0];
            split_store8(smem + AT_KH, smem + AT_KL, (unsigned)(j*LDP + d0)*2,
                         *(const float4*)pk, *(const float4*)(pk + 4));
            const float* pv = &g_vals[((size_t)bh*NSEQ + jt*64 + j)*DH + d0];
            split_store8(smem + AT_VH, smem + AT_VL, (unsigned)(j*LDP + d0)*2,
                         *(const float4*)pv, *(const float4*)(pv + 4));
        }
        __syncthreads();
        // S^T mma: A=K [kv][d], B=Q^T [d][q]
        float s[2][4][4] = {};
#pragma unroll
        for (int ks = 0; ks < 4; ks++) {
            int k0 = ks * 16;
            unsigned ah[2][4], al[2][4], bh2[4][2], bl2[4][2];
#pragma unroll
            for (int mt = 0; mt < 2; mt++) {
                int row = wmS*32 + mt*16 + (lane & 15);
                unsigned off = (unsigned)(row*LDP + k0 + (lane >> 4)*8) * 2;
                ldsm_x4(ah[mt][0], ah[mt][1], ah[mt][2], ah[mt][3], sb + AT_KH + off);
                ldsm_x4(al[mt][0], al[mt][1], al[mt][2], al[mt][3], sb + AT_KL + off);
            }
#pragma unroll
            for (int np = 0; np < 2; np++) {
                int n0 = wnS*32 + np*16;
                unsigned off = bx4t_off(k0, n0, LDQT, lane);
                ldsm_x4t(bh2[2*np][0], bh2[2*np][1], bh2[2*np+1][0], bh2[2*np+1][1],
                         sb + AT_QTH + off);
                ldsm_x4t(bl2[2*np][0], bl2[2*np][1], bl2[2*np+1][0], bl2[2*np+1][1],
                         sb + AT_QTL + off);
            }
#pragma unroll
            for (int mt = 0; mt < 2; mt++)
#pragma unroll
                for (int nt = 0; nt < 4; nt++) {
                    mma_bf16(s[mt][nt], ah[mt][0], ah[mt][1], ah[mt][2], ah[mt][3],
                             bh2[nt][0], bh2[nt][1]);
                    mma_bf16(s[mt][nt], ah[mt][0], ah[mt][1], ah[mt][2], ah[mt][3],
                             bl2[nt][0], bl2[nt][1]);
                    mma_bf16(s[mt][nt], al[mt][0], al[mt][1], al[mt][2], al[mt][3],
                             bh2[nt][0], bh2[nt][1]);
                }
        }
        // causal mask + store S^T -> Ps[q][kv]
        bool diag = (jt*64 + 63 > qbase);
#pragma unroll
        for (int mt = 0; mt < 2; mt++)
#pragma unroll
            for (int nt = 0; nt < 4; nt++) {
                int kvr = wmS*32 + mt*16 + (lane >> 2);
                int q0  = wnS*32 + nt*8 + (lane & 3)*2;
                if (diag) {
                    int kg = jt*64 + kvr, qg = qbase + q0;
                    if (kg > qg)       s[mt][nt][0] = -1e30f;
                    if (kg > qg+1)     s[mt][nt][1] = -1e30f;
                    if (kg+8 > qg)     s[mt][nt][2] = -1e30f;
                    if (kg+8 > qg+1)   s[mt][nt][3] = -1e30f;
                }
                Ps[q0*LDPS + kvr]       = s[mt][nt][0];
                Ps[(q0+1)*LDPS + kvr]   = s[mt][nt][1];
                Ps[q0*LDPS + kvr+8]     = s[mt][nt][2];
                Ps[(q0+1)*LDPS + kvr+8] = s[mt][nt][3];
            }
        __syncthreads();
        // online softmax (2 thr/row) + emit P as split bf16 [q][kv]
        {
            int row = tid >> 1, half = tid & 1;
            float* P = &Ps[row*LDPS + half*32];
            float mx = m_s[row];
#pragma unroll 8
            for (int j2 = 0; j2 < 32; j2++) mx = fmaxf(mx, P[j2]);
            mx = fmaxf(mx, __shfl_xor_sync(0xffffffffu, mx, 1));
            float sum = 0.f;
            __nv_bfloat162* PH2 = (__nv_bfloat162*)(smem + AT_PH + (size_t)(row*LDP + half*32)*2);
            __nv_bfloat162* PL2 = (__nv_bfloat162*)(smem + AT_PL + (size_t)(row*LDP + half*32)*2);
#pragma unroll 4
            for (int j2 = 0; j2 < 32; j2 += 2) {
                float p0 = __expf(P[j2] - mx);
                float p1 = __expf(P[j2+1] - mx);
                sum += p0 + p1;
                __nv_bfloat16 h0 = __float2bfloat16_rn(p0);
                __nv_bfloat16 h1 = __float2bfloat16_rn(p1);
                PH2[j2 >> 1] = __halves2bfloat162(h0, h1);
                PL2[j2 >> 1] = __floats2bfloat162_rn(p0 - __bfloat162float(h0),
                                                     p1 - __bfloat162float(h1));
            }
            sum += __shfl_xor_sync(0xffffffffu, sum, 1);
            if (half == 0) {
                float mo = m_s[row];
                float f = __expf(mo - mx);
                m_s[row] = mx;
                l_s[row] = l_s[row]*f + sum;
                f_s[row] = f;
            }
        }
        __syncthreads();
        // rescale O and accumulate P·V
#pragma unroll
        for (int mt = 0; mt < 2; mt++) {
            int r0 = wm*32 + mt*16 + (lane >> 2);
            float f0 = f_s[r0], f1 = f_s[r0 + 8];
#pragma unroll
            for (int nt = 0; nt < 4; nt++) {
                o[mt][nt][0] *= f0; o[mt][nt][1] *= f0;
                o[mt][nt][2] *= f1; o[mt][nt][3] *= f1;
            }
        }
#pragma unroll
        for (int ks = 0; ks < 4; ks++) {
            int k0 = ks * 16;
            unsigned ah[2][4], al[2][4], bh2[4][2], bl2[4][2];
#pragma unroll
            for (int mt = 0; mt < 2; mt++) {
                int row = wm*32 + mt*16 + (lane & 15);
                unsigned off = (unsigned)(row*LDP + k0 + (lane >> 4)*8) * 2;
                ldsm_x4(ah[mt][0], ah[mt][1], ah[mt][2], ah[mt][3], sb + AT_PH + off);
                ldsm_x4(al[mt][0], al[mt][1], al[mt][2], al[mt][3], sb + AT_PL + off);
            }
#pragma unroll
            for (int np = 0; np < 2; np++) {
                int n0 = wn*32 + np*16;
                unsigned off = bx4t_off(k0, n0, LDP, lane);
                ldsm_x4t(bh2[2*np][0], bh2[2*np][1], bh2[2*np+1][0], bh2[2*np+1][1],
                         sb + AT_VH + off);
                ldsm_x4t(bl2[2*np][0], bl2[2*np][1], bl2[2*np+1][0], bl2[2*np+1][1],
                         sb + AT_VL + off);
            }
#pragma unroll
            for (int mt = 0; mt < 2; mt++)
#pragma unroll
                for (int nt = 0; nt < 4; nt++) {
                    mma_bf16(o[mt][nt], ah[mt][0], ah[mt][1], ah[mt][2], ah[mt][3],
                             bh2[nt][0], bh2[nt][1]);
                    mma_bf16(o[mt][nt], ah[mt][0], ah[mt][1], ah[mt][2], ah[mt][3],
                             bl2[nt][0], bl2[nt][1]);
                    mma_bf16(o[mt][nt], al[mt][0], al[mt][1], al[mt][2], al[mt][3],
                             bh2[nt][0], bh2[nt][1]);
                }
        }
    }
    // epilogue: divide by l, write
#pragma unroll
    for (int mt = 0; mt < 2; mt++) {
        int r0 = wm*32 + mt*16 + (lane >> 2);
        float inv0 = 1.f / l_s[r0], inv1 = 1.f / l_s[r0 + 8];
#pragma unroll
        for (int nt = 0; nt < 4; nt++) {
            int col = wn*32 + nt*8 + (lane & 3)*2;
            *(float2*)&g_attn[((size_t)bh*NSEQ + qbase + r0)*DH + col] =
                make_float2(o[mt][nt][0]*inv0, o[mt][nt][1]*inv0);
            *(float2*)&g_attn[((size_t)bh*NSEQ + qbase + r0 + 8)*DH + col] =
                make_float2(o[mt][nt][2]*inv1, o[mt][nt][3]*inv1);
        }
    }
}

// ---------------- kernel 6: output-expert GEMM via warp MMA, 4 col-tiles/block ----------------
__global__ void __launch_bounds__(256, 2)
outt_kernel(const float* __restrict__ oexp) {
    extern __shared__ __align__(128) char smem[];
    int he = blockIdx.x; int h = he >> 3, e = he & 7;
    int cnt = g_cnt[he];
    int start = blockIdx.y * 128;
    if (start >= cnt) return;
    int ct0 = blockIdx.z * 4;            // 4 blocks x 4 tiles of 64 cols
    unsigned sb = smem_u32(smem);
    int tid = threadIdx.x, wid = tid >> 5, lane = tid & 31;
    int wm = wid & 3, wn = wid >> 2;
    int* ts = (int*)(smem + SM_TS);
    float* gts = (float*)(smem + SM_GTS);
    if (tid < 128) {
        int t = (start + tid < cnt) ? g_list[(size_t)he*TTOK + start + tid] : -1;
        ts[tid] = t;
        gts[tid] = (t >= 0) ? g_gate[(size_t)((t>>11)*NH + h)*NSEQ + (t & 2047)] : 0.f;
    }
    __syncthreads();
    const float* B = oexp + (size_t)(e*NH + h)*DH*DIMM;

    // stage A once (gated attn [128 tok][64 dh])
#pragma unroll
    for (int r = 0; r < 4; r++) {
        int task = tid + 256*r;
        int row = task >> 3, kg = task & 7;
        int t = ts[row];
        float4 v0 = make_float4(0.f,0.f,0.f,0.f), v1 = v0;
        if (t >= 0) {
            size_t base = ((size_t)(t>>11)*NH + h)*NSEQ + (t & 2047);
            const float* p = &g_attn[base*DH + kg*8];
            v0 = *(const float4*)p; v1 = *(const float4*)(p + 4);
            float g = gts[row];
            v0.x*=g; v0.y*=g; v0.z*=g; v0.w*=g;
            v1.x*=g; v1.y*=g; v1.z*=g; v1.w*=g;
        }
        split_store8(smem + SM_AHI, smem + SM_ALO, (unsigned)(row*LDA + kg*8)*2, v0, v1);
    }

    for (int i = 0; i < 4; i++) {
        int ct = ct0 + i;
        __syncthreads();                 // A visible / previous B consumed
#pragma unroll
        for (int r = 0; r < 2; r++) {
            int task = tid + 256*r;
            int krow = task >> 3, ng = task & 7;
            const float* p = B + (size_t)krow*DIMM + ct*64 + ng*8;
            split_store8(smem + SM_BHI, smem + SM_BLO, (unsigned)(krow*LDA + ng*8)*2,
                         *(const float4*)p, *(const float4*)(p + 4));
        }
        __syncthreads();
        float c[2][4][4] = {};
        mma_chunk(c, sb, wm, wn, lane);
#pragma unroll
        for (int mt = 0; mt < 2; mt++)
#pragma unroll
            for (int nt = 0; nt < 4; nt++) {
                int col = ct*64 + wn*32 + nt*8 + (lane & 3)*2;
                int r0 = wm*32 + mt*16 + (lane >> 2);
                int t0 = ts[r0], t1 = ts[r0 + 8];
                if (t0 >= 0) {
                    size_t base = ((size_t)(t0>>11)*NH + h)*NSEQ + (t0 & 2047);
                    *(float2*)&g_outh[base*DIMM + col] = make_float2(c[mt][nt][0], c[mt][nt][1]);
                }
                if (t1 >= 0) {
                    size_t base = ((size_t)(t1>>11)*NH + h)*NSEQ + (t1 & 2047);
                    *(float2*)&g_outh[base*DIMM + col] = make_float2(c[mt][nt][2], c[mt][nt][3]);
                }
            }
    }
}

// ---------------- kernel 7: sum over heads ----------------
__global__ void reduce_kernel(float* __restrict__ out) {
    int idx = blockIdx.x * blockDim.x + threadIdx.x;
    const int total = TTOK * (DIMM/4);
    const float4* ph = (const float4*)g_outh;
    float4* po = (float4*)out;
    for (; idx < total; idx += gridDim.x * blockDim.x) {
        int t = idx >> 8;
        int d4 = idx & 255;
        int b_ = t >> 11, n = t & 2047;
        float4 s = make_float4(0.f,0.f,0.f,0.f);
#pragma unroll
        for (int h = 0; h < NH; h++) {
            float4 v = ph[((size_t)(b_*NH + h)*NSEQ + n)*256 + d4];
            s.x += v.x; s.y += v.y; s.z += v.z; s.w += v.w;
        }
        po[idx] = s;
    }
}

// ---------------- launch ----------------
extern "C" void kernel_launch(void* const* d_in, const int* in_sizes, int n_in,
                              void* d_out, int out_size) {
    const float* x  = (const float*)d_in[0];
    const float* wq = (const float*)d_in[1];
    const float* wk = (const float*)d_in[2];
    const float* wg = (const float*)d_in[3];
    const float* ve = (const float*)d_in[4];
    const float* oe = (const float*)d_in[5];
    float* out = (float*)d_out;

    cudaFuncSetAttribute(attn_kernel,
                         cudaFuncAttributeMaxDynamicSharedMemorySize, ATTN2_SMEM);
    cudaFuncSetAttribute(projt_kernel,
                         cudaFuncAttributeMaxDynamicSharedMemorySize, TENS_SMEM);
    cudaFuncSetAttribute(valt_kernel,
                         cudaFuncAttributeMaxDynamicSharedMemorySize, TENS_SMEM);
    cudaFuncSetAttribute(outt_kernel,
                         cudaFuncAttributeMaxDynamicSharedMemorySize, TENS_SMEM);

    init_kernel<<<1, 64>>>();
    glogit_kernel<<<dim3(TTOK/128, 8), 256>>>(x, wg);
    gate_kernel<<<(TTOK*NH)/64, 64>>>();
    projt_kernel<<<dim3(TTOK/128, 16), 256, TENS_SMEM>>>(x, wq, wk);
    valt_kernel<<<dim3(NH*NE, TTOK/128), 256, TENS_SMEM>>>(x, ve);
    attn_kernel<<<dim3(BH, NSEQ/128), 256, ATTN2_SMEM>>>();
    outt_kernel<<<dim3(NH*NE, TTOK/128, DIMM/256), 256, TENS_SMEM>>>(oe);
    reduce_kernel<<<2048, 256>>>(out);
}